// round 7
// baseline (speedup 1.0000x reference)
#include <cuda_runtime.h>
#include <cuda_bf16.h>

#define NBS   256
#define NEMB  128
#define NP    1024
#define NMODE 256

#define S2f  1.41421356237f
#define IS2f 0.70710678119f

// ---------------- device scratch ----------------
__device__ float2 g_tw[32];
__device__ float2 g_ytab[512];
__device__ float  g_cpb[8 * 256];
__device__ float  g_attn[16 * 8 * 256];
__device__ float  g_gram[16 * 128 * 256];                // spatial - freq/1024 combined
__device__ float2 g_Xf [NBS * NEMB * NMODE];             // fwd DFT [bs*c][m]
__device__ __nv_bfloat16 g_Ab [256L * 256 * 2 * 256];    // A split [m][bs][h][re|im k]
__device__ __nv_bfloat16 g_Wqc[256L * 3 * 2 * 128 * 2 * 128]; // compact qkv W
__device__ __nv_bfloat16 g_Woc[256L * 2 * 128 * 2 * 128];     // compact out W
__device__ float  g_C2o[256L * 256 * 256];               // out GEMM out [m][bs][n]
__device__ __nv_bfloat16 g_Fqh[NBS * 512L * NEMB];       // bf16 features [bs][2m+p][c]
__device__ __nv_bfloat16 g_Fkh[NBS * 512L * NEMB];
__device__ float  g_VeR[NBS * NMODE * NEMB];
__device__ float  g_VeI[NBS * NMODE * NEMB];

__device__ __forceinline__ void bf_split(float v, __nv_bfloat16& h, __nv_bfloat16& l) {
    h = __float2bfloat16_rn(v);
    l = __float2bfloat16_rn(v - __bfloat162float(h));
}

// ---------------- init twiddles ----------------
__global__ void k_init() {
    int t = threadIdx.x;  // 512
    if (t < 32) {
        float s, c;
        sincospif((float)t * (1.0f / 16.0f), &s, &c);
        g_tw[t] = make_float2(c, s);
    }
    int ky = t >> 5, v = t & 31;
    float2 w;
    if (ky == 0) w = make_float2(0.5f, 0.0f);
    else { float s, c; sincospif((float)(ky * v) * (1.0f / 16.0f), &s, &c); w = make_float2(c, s); }
    g_ytab[t] = w;
}

// ---------------- log-CPB ----------------
__global__ void k_cpb(const float* __restrict__ w1, const float* __restrict__ b1,
                      const float* __restrict__ w2) {
    int t = threadIdx.x;
    int i = t >> 4, j = t & 15;
    float rx = (float)((i >> 2) - (j >> 2));
    float ry = (float)((i & 3) - (j & 3));
    float ax = log2f(1.0f + fabsf(rx)) * (8.0f / 3.0f);
    float ay = log2f(1.0f + fabsf(ry)) * (8.0f / 3.0f);
    ax = copysignf(ax, rx); ay = copysignf(ay, ry);
    float acc[8];
#pragma unroll
    for (int q = 0; q < 8; q++) acc[q] = 0.0f;
    for (int h = 0; h < 512; h++) {
        float hv = fmaxf(ax * w1[h] + ay * w1[512 + h] + b1[h], 0.0f);
#pragma unroll
        for (int q = 0; q < 8; q++) acc[q] += hv * w2[h * 8 + q];
    }
#pragma unroll
    for (int q = 0; q < 8; q++) g_cpb[(q * 16 + i) * 16 + j] = acc[q];
}

// ---------------- W prep: fold residual+mode weights, compact split planes ----------------
__global__ void k_wprep(const float* __restrict__ wr, const float* __restrict__ wi, int which) {
    int No = which ? 128 : 384;
    int o = blockIdx.x, m0 = blockIdx.y << 5;
    __shared__ float sr[128][33], si[128][33];
    int t = threadIdx.x;  // 256
    int mi = t & 31, c0 = t >> 5;
#pragma unroll
    for (int it = 0; it < 16; it++) {
        int c = (it << 3) + c0;
        long src = ((long)c * No + o) * 256 + m0 + mi;
        sr[c][mi] = wr[src];
        si[c][mi] = wi[src];
    }
    __syncthreads();
    int w = t >> 5, lane = t & 31;
    int oI = o >> 7, n = o & 127;
#pragma unroll
    for (int ml = 0; ml < 4; ml++) {
        int mi2 = (w << 2) + ml;
        long m = m0 + mi2;
        int ky = (int)(m & 15);
        float a, bco; int zim;
        if (which) { a = 0.0f; bco = 1.0f; zim = 0; }
        else if (oI == 2) {
            a = 1.0f; bco = (m == 0) ? 1.0f : ((ky == 0) ? 0.5f : 1.0f); zim = (m == 0);
        } else {
            if (m == 0)       { a = 1.0f;  bco = 1.0f;  zim = 1; }
            else if (ky == 0) { a = S2f;   bco = IS2f;  zim = 0; }
            else              { a = S2f;   bco = S2f;   zim = 0; }
        }
        long base = which ? ((m * 2) * 128 + n) * 2 * 128
                          : (((m * 3 + oI) * 2) * 128 + n) * 2 * 128;
        long pstride = (long)128 * 2 * 128;
        __nv_bfloat16* dst = which ? g_Woc : g_Wqc;
#pragma unroll
        for (int kl = 0; kl < 4; kl++) {
            int k = (kl << 5) + lane;
            float vr = bco * sr[k][mi2] + ((k == n) ? a : 0.0f);
            if (which && k == n) vr = sr[k][mi2];
            float vi = zim ? 0.0f : bco * si[k][mi2];
            __nv_bfloat16 h, l;
            bf_split(vr, h, l);
            dst[base + k] = h;
            dst[base + 128 + k] = l;
            bf_split(vi, h, l);
            dst[base + pstride + k] = h;
            dst[base + pstride + 128 + k] = l;
        }
    }
}

// ---------------- fused: shift-gather + DFT(16 tokens) + spatial gram + freq gram ----------------
// grid (16 b, 128 c), 512 threads, dynamic smem: tiles[16][1028] f32 + sX[16][258] float2
__global__ void __launch_bounds__(512) k_fg(const float* __restrict__ seq) {
    extern __shared__ float dyn[];
    float*  tiles = dyn;                              // 16 x 1028
    float2* sX    = (float2*)(dyn + 16 * 1028);       // 16 x 258
    __shared__ float2 T[16][33];
    __shared__ float2 tw[32];
    int b = blockIdx.x, c = blockIdx.y;
    int t = threadIdx.x;  // 512
    if (t < 32) tw[t] = g_tw[t];

    // load 16 shifted tiles
#pragma unroll
    for (int k = 0; k < 32; k++) {
        int e = t + (k << 9);
        int s = e >> 10, p = e & 1023;
        int u = p >> 5, v = p & 31;
        int qx = s >> 2, qy = s & 3;
        int I = ((qx << 5) + u + 16) & 127;
        int J = ((qy << 5) + v + 16) & 127;
        int s2 = ((I >> 5) << 2) | (J >> 5);
        tiles[s * 1028 + p] = seq[(((b * 16 + s2) * 128 + c) * NP) + ((I & 31) << 5) + (J & 31)];
    }
    __syncthreads();

    // DFT per token
    for (int s = 0; s < 16; s++) {
        {   // stage 1: 512 outputs, one per thread
            int kx = t >> 5, v = t & 31;
            float tr = 0.0f, ti = 0.0f;
            int a = 0;
            const float* xs = tiles + s * 1028;
#pragma unroll
            for (int u = 0; u < 32; u++) {
                float x = xs[(u << 5) + v];
                float2 w = tw[a];
                tr += x * w.x; ti -= x * w.y;
                a = (a + kx) & 31;
            }
            T[kx][v] = make_float2(tr, ti);
        }
        __syncthreads();
        if (t < 256) {
            int kx = t >> 4, ky = t & 15;
            float xr = 0.0f, xi = 0.0f;
            int a = 0;
#pragma unroll
            for (int v = 0; v < 32; v++) {
                float2 tv = T[kx][v];
                float2 w = tw[a];
                xr += tv.x * w.x + tv.y * w.y;
                xi += tv.y * w.x - tv.x * w.y;
                a = (a + ky) & 31;
            }
            float2 X = make_float2(xr, xi);
            sX[s * 258 + t] = X;
            g_Xf[(long)((b * 16 + s) * 128 + c) * 256 + t] = X;
        }
        __syncthreads();
    }

    // spatial gram + freq gram (register-blocked 4x4 pairs, 32 groups)
    int ti = (t >> 2) & 3, tj = t & 3, g = t >> 4;
    float accS[4][4], accF[4][4];
#pragma unroll
    for (int ii = 0; ii < 4; ii++)
#pragma unroll
        for (int jj = 0; jj < 4; jj++) { accS[ii][jj] = 0.0f; accF[ii][jj] = 0.0f; }

#pragma unroll
    for (int w = 0; w < 32; w++) {
        int pl = (g << 5) + w;
        float av[4], bv[4];
#pragma unroll
        for (int ii = 0; ii < 4; ii++) av[ii] = tiles[(ti * 4 + ii) * 1028 + pl];
#pragma unroll
        for (int jj = 0; jj < 4; jj++) bv[jj] = tiles[(tj * 4 + jj) * 1028 + pl];
#pragma unroll
        for (int ii = 0; ii < 4; ii++)
#pragma unroll
            for (int jj = 0; jj < 4; jj++) accS[ii][jj] += av[ii] * bv[jj];
    }
#pragma unroll
    for (int mm = 0; mm < 8; mm++) {
        int m = (g << 3) + mm;
        float2 xv[4], yv[4];
#pragma unroll
        for (int ii = 0; ii < 4; ii++) xv[ii] = sX[(ti * 4 + ii) * 258 + m];
#pragma unroll
        for (int jj = 0; jj < 4; jj++) yv[jj] = sX[(tj * 4 + jj) * 258 + m];
#pragma unroll
        for (int ii = 0; ii < 4; ii++)
#pragma unroll
            for (int jj = 0; jj < 4; jj++)
                accF[ii][jj] += 2.0f * (xv[ii].x * yv[jj].x + xv[ii].y * yv[jj].y);
    }
    __syncthreads();
    // partials: combined = accS - accF/1024, pad 33
#pragma unroll
    for (int ii = 0; ii < 4; ii++)
#pragma unroll
        for (int jj = 0; jj < 4; jj++) {
            int pp = ((ti * 4 + ii) << 4) + tj * 4 + jj;
            tiles[pp * 33 + g] = accS[ii][jj] - accF[ii][jj] * (1.0f / 1024.0f);
        }
    __syncthreads();
    if (t < 256) {
        float ssum = 0.0f;
#pragma unroll
        for (int g2 = 0; g2 < 32; g2++) ssum += tiles[t * 33 + g2];
        // DC: loop counted 2*(re+im); correct term is re only (im exactly 0) -> add back re/1024
        int i = t >> 4, j = t & 15;
        ssum += sX[i * 258].x * sX[j * 258].x * (1.0f / 1024.0f);
        g_gram[(((b << 7) + c) << 8) + t] = ssum;
    }
}

// ---------------- A prep: transpose Xf -> realified split Ab ----------------
__global__ void k_prepA() {
    __shared__ float2 tile[32][33];
    int c0 = blockIdx.x << 5, r0 = blockIdx.y << 5;
    int tx = threadIdx.x, ty = threadIdx.y;
#pragma unroll
    for (int q = 0; q < 4; q++)
        tile[ty + (q << 3)][tx] = g_Xf[(long)(r0 + ty + (q << 3)) * 256 + c0 + tx];
    __syncthreads();
#pragma unroll
    for (int q = 0; q < 4; q++) {
        int m = c0 + ty + (q << 3);
        int row = r0 + tx;
        int bs = row >> 7, c = row & 127;
        float2 v = tile[tx][ty + (q << 3)];
        long base = ((long)m * 256 + bs) * 2 * 256;
        __nv_bfloat16 h, l;
        bf_split(v.x, h, l); g_Ab[base + c] = h;        g_Ab[base + 256 + c] = l;
        bf_split(v.y, h, l); g_Ab[base + 128 + c] = h;  g_Ab[base + 384 + c] = l;
    }
}

// ---------------- tensor-core GEMM with compact-W expansion ----------------
template <int NT>
__global__ void __launch_bounds__(256) k_gemm() {
    __shared__ __nv_bfloat16 As[2][128][40];
    __shared__ __nv_bfloat16 Bs[2][128][40];

    int nb = blockIdx.x, mb = blockIdx.y, mo = blockIdx.z;
    int t = threadIdx.x;
    int wid = t >> 5, lane = t & 31;
    int wm = wid & 1, wn = wid >> 1;
    int g = lane >> 2, tq = lane & 3;

    int isImOut = (NT == 768) ? (nb >= 3 ? 1 : 0) : nb;
    int oI      = (NT == 768) ? (nb - (isImOut ? 3 : 0)) : 0;
    const __nv_bfloat16* Wm = (NT == 768)
        ? (g_Wqc + (long)mo * (3L * 2 * 128 * 2 * 128) + (long)oI * (2L * 128 * 2 * 128))
        : (g_Woc + (long)mo * (2L * 128 * 2 * 128));

    float acc[4][4][4];
#pragma unroll
    for (int i = 0; i < 4; i++)
#pragma unroll
        for (int j = 0; j < 4; j++)
#pragma unroll
            for (int r = 0; r < 4; r++) acc[i][j][r] = 0.0f;

    const __nv_bfloat16* Abase = g_Ab + ((long)mo * 256 + mb * 128) * 2 * 256;

    int lr = t & 127, lh = t >> 7;
    for (int k0 = 0; k0 < 256; k0 += 32) {
        {
            const float4* sa = (const float4*)(Abase + ((long)lr * 2 + lh) * 256 + k0);
            float4* da = (float4*)&As[lh][lr][0];
            da[0] = sa[0]; da[1] = sa[1]; da[2] = sa[2]; da[3] = sa[3];

            int isImK = (k0 >= 128) ? 1 : 0;
            int p = isImK ^ isImOut;
            unsigned flip = (isImK && !isImOut) ? 0x80008000u : 0u;
            const uint4* sb = (const uint4*)(Wm + ((long)p * 128 + lr) * 2 * 128 + (long)lh * 128 + (k0 & 127));
            uint4* db = (uint4*)&Bs[lh][lr][0];
#pragma unroll
            for (int q = 0; q < 4; q++) {
                uint4 v = sb[q];
                v.x ^= flip; v.y ^= flip; v.z ^= flip; v.w ^= flip;
                db[q] = v;
            }
        }
        __syncthreads();
#pragma unroll
        for (int ks = 0; ks < 2; ks++) {
            unsigned ah[4][4], al[4][4], bh[4][2], bl[4][2];
            int kb = ks * 16 + 2 * tq;
#pragma unroll
            for (int mt = 0; mt < 4; mt++) {
                int row = wm * 64 + mt * 16 + g;
                ah[mt][0] = *(const unsigned*)&As[0][row][kb];
                ah[mt][1] = *(const unsigned*)&As[0][row + 8][kb];
                ah[mt][2] = *(const unsigned*)&As[0][row][kb + 8];
                ah[mt][3] = *(const unsigned*)&As[0][row + 8][kb + 8];
                al[mt][0] = *(const unsigned*)&As[1][row][kb];
                al[mt][1] = *(const unsigned*)&As[1][row + 8][kb];
                al[mt][2] = *(const unsigned*)&As[1][row][kb + 8];
                al[mt][3] = *(const unsigned*)&As[1][row + 8][kb + 8];
            }
#pragma unroll
            for (int nt = 0; nt < 4; nt++) {
                int col = wn * 32 + nt * 8 + g;
                bh[nt][0] = *(const unsigned*)&Bs[0][col][kb];
                bh[nt][1] = *(const unsigned*)&Bs[0][col][kb + 8];
                bl[nt][0] = *(const unsigned*)&Bs[1][col][kb];
                bl[nt][1] = *(const unsigned*)&Bs[1][col][kb + 8];
            }
#define MMA(d, a, b0, b1)                                                     \
    asm volatile("mma.sync.aligned.m16n8k16.row.col.f32.bf16.bf16.f32 "       \
                 "{%0,%1,%2,%3}, {%4,%5,%6,%7}, {%8,%9}, {%0,%1,%2,%3};"      \
                 : "+f"(d[0]), "+f"(d[1]), "+f"(d[2]), "+f"(d[3])             \
                 : "r"(a[0]), "r"(a[1]), "r"(a[2]), "r"(a[3]), "r"(b0), "r"(b1))
#pragma unroll
            for (int mt = 0; mt < 4; mt++)
#pragma unroll
                for (int nt = 0; nt < 4; nt++) {
                    MMA(acc[mt][nt], ah[mt], bh[nt][0], bh[nt][1]);
                    MMA(acc[mt][nt], ah[mt], bl[nt][0], bl[nt][1]);
                    MMA(acc[mt][nt], al[mt], bh[nt][0], bh[nt][1]);
                }
#undef MMA
        }
        __syncthreads();
    }

    if (NT == 768) {
#pragma unroll
        for (int mt = 0; mt < 4; mt++)
#pragma unroll
            for (int nt = 0; nt < 4; nt++) {
                int c = wn * 32 + nt * 8 + 2 * tq;
#pragma unroll
                for (int rr = 0; rr < 2; rr++) {
                    int bs = mb * 128 + wm * 64 + mt * 16 + g + rr * 8;
                    float2 val = make_float2(acc[mt][nt][rr * 2], acc[mt][nt][rr * 2 + 1]);
                    long fidx = (long)bs * 65536 + (2L * mo + isImOut) * 128 + c;
                    if (oI == 0)
                        *(__nv_bfloat162*)&g_Fqh[fidx] = __floats2bfloat162_rn(val.x, val.y);
                    else if (oI == 1)
                        *(__nv_bfloat162*)&g_Fkh[fidx] = __floats2bfloat162_rn(val.x, val.y);
                    else {
                        float* vp = isImOut ? g_VeI : g_VeR;
                        *(float2*)&vp[((long)bs * 256 + mo) * 128 + c] = val;
                    }
                }
            }
    } else {
#pragma unroll
        for (int mt = 0; mt < 4; mt++)
#pragma unroll
            for (int nt = 0; nt < 4; nt++) {
                int row = mb * 128 + wm * 64 + mt * 16 + g;
                long base = ((long)mo * 256 + row) * NT + nb * 128 + wn * 32 + nt * 8 + 2 * tq;
                *(float2*)&g_C2o[base] = make_float2(acc[mt][nt][0], acc[mt][nt][1]);
                *(float2*)&g_C2o[base + 8L * NT] = make_float2(acc[mt][nt][2], acc[mt][nt][3]);
            }
    }
}

// ---------------- scores + bias + softmax (bf16 features) ----------------
__global__ void k_scores(const float* __restrict__ amask) {
    int b = blockIdx.x, n = blockIdx.y;
    __shared__ float sq[16 * 132], sk[16 * 132];
    int t = threadIdx.x;
    int i = t >> 4, j = t & 15;
    float D = 0.0f;

    for (int ch = 0; ch < 64; ch++) {
#pragma unroll
        for (int k = 0; k < 4; k++) {
            int e = t + (k << 8);                 // 1024 bf162 units
            int dp = e & 7, mcL = (e >> 3) & 7, ii = e >> 6;
            long ga = ((long)((b << 4) + ii) * 512 + (ch << 3) + mcL) * 128 + (n << 4) + (dp << 1);
            int sa = ii * 132 + (mcL << 4) + (dp << 1);
            __nv_bfloat162 q2 = *(const __nv_bfloat162*)&g_Fqh[ga];
            __nv_bfloat162 k2 = *(const __nv_bfloat162*)&g_Fkh[ga];
            float2 qf = __bfloat1622float2(q2);
            float2 kf = __bfloat1622float2(k2);
            *(float2*)&sq[sa] = qf;
            *(float2*)&sk[sa] = kf;
        }
        __syncthreads();
        const float4* aq = (const float4*)(sq + i * 132);
        const float4* ak = (const float4*)(sk + j * 132);
#pragma unroll
        for (int r = 0; r < 32; r++) {
            float4 a = aq[r], bb = ak[r];
            D += a.x * bb.x + a.y * bb.y + a.z * bb.z + a.w * bb.w;
        }
        __syncthreads();
    }

    float gsum = 0.0f;
#pragma unroll
    for (int d = 0; d < 16; d++)
        gsum += g_gram[(((b << 7) + (n << 4) + d) << 8) + t];

    float s = (gsum + D * (1.0f / 1024.0f)) * (1.0f / 4096.0f);
    s += amask[(((b & 3) * 8 + n) << 8) + t] + g_cpb[(n << 8) + t];
    float mx = s;
#pragma unroll
    for (int off = 8; off; off >>= 1) mx = fmaxf(mx, __shfl_xor_sync(0xffffffffu, mx, off));
    float e = expf(s - mx);
    float su = e;
#pragma unroll
    for (int off = 8; off; off >>= 1) su += __shfl_xor_sync(0xffffffffu, su, off);
    g_attn[((b * 8 + n) << 8) + t] = e / su;
}

// ---------------- attn x Veff -> realified split A for out GEMM ----------------
__global__ void k_av() {
    int b = blockIdx.x, mch = blockIdx.y;
    __shared__ float2 sV[16][2][128];
    __shared__ float sA[2048];
    int t = threadIdx.x;
#pragma unroll
    for (int k = 0; k < 8; k++) sA[t + (k << 8)] = g_attn[b * 2048 + t + (k << 8)];
#pragma unroll
    for (int k = 0; k < 16; k++) {
        int e = t + (k << 8);
        int c = e & 127, mo = (e >> 7) & 1, j = e >> 8;
        long vi = ((long)((b << 4) + j) * 256 + (mch << 1) + mo) * 128 + c;
        sV[j][mo][c] = make_float2(g_VeR[vi], g_VeI[vi]);
    }
    __syncthreads();
    int c = t & 127, mo = t >> 7;
    int n = c >> 4;
    float2 acc[16];
#pragma unroll
    for (int ii = 0; ii < 16; ii++) acc[ii] = make_float2(0.0f, 0.0f);
#pragma unroll
    for (int jj = 0; jj < 16; jj++) {
        float2 v = sV[jj][mo][c];
#pragma unroll
        for (int ii = 0; ii < 16; ii++) {
            float a = sA[(n << 8) + (ii << 4) + jj];
            acc[ii].x += a * v.x;
            acc[ii].y += a * v.y;
        }
    }
    int m = (mch << 1) + mo;
#pragma unroll
    for (int ii = 0; ii < 16; ii++) {
        int bs = (b << 4) + ii;
        long base = ((long)m * 256 + bs) * 2 * 256;
        __nv_bfloat16 h, l;
        bf_split(acc[ii].x, h, l); g_Ab[base + c] = h;       g_Ab[base + 256 + c] = l;
        bf_split(acc[ii].y, h, l); g_Ab[base + 128 + c] = h; g_Ab[base + 384 + c] = l;
    }
}

// ---------------- inverse irfft2, 16 channels/block, direct C2o read, fused un-shift ----------------
__global__ void k_inv2(float* __restrict__ dout) {
    int bs = blockIdx.x, og = blockIdx.y;     // og: 8 groups of 16 channels
    __shared__ float2 sS[16][257];            // [o][m]
    __shared__ float2 Gs[32][17];
    __shared__ float2 ytabs[512];
    __shared__ float2 tw[32];
    int t = threadIdx.x;                      // 256
    if (t < 32) tw[t] = g_tw[t];
    ytabs[t]       = g_ytab[t];
    ytabs[t + 256] = g_ytab[t + 256];
    {
        long base = (long)t * 65536 + bs * 256 + og * 16;   // t = mode
        float re[16], im[16];
#pragma unroll
        for (int q = 0; q < 4; q++) {
            *(float4*)&re[q * 4] = *(const float4*)&g_C2o[base + q * 4];
            *(float4*)&im[q * 4] = *(const float4*)&g_C2o[base + 128 + q * 4];
        }
#pragma unroll
        for (int ol = 0; ol < 16; ol++)
            sS[ol][t] = make_float2(re[ol], im[ol]);
    }
    __syncthreads();

    int b = bs >> 4, s = bs & 15, qx = s >> 2, qy = s & 3;
    for (int o = 0; o < 16; o++) {
#pragma unroll
        for (int q = 0; q < 2; q++) {
            int idx = t + (q << 8);
            int u = idx >> 4, ky = idx & 15;
            float gr = 0.0f, gi = 0.0f;
            int a = 0;
#pragma unroll
            for (int kx = 0; kx < 16; kx++) {
                float2 sv = sS[o][(kx << 4) + ky];
                float2 w = tw[a];
                gr += sv.x * w.x - sv.y * w.y;
                gi += sv.x * w.y + sv.y * w.x;
                a = (a + u) & 31;
            }
            Gs[u][ky] = make_float2(gr, gi);
        }
        __syncthreads();
#pragma unroll
        for (int q = 0; q < 4; q++) {
            int idx = t + (q << 8);
            int u = idx >> 5, v = idx & 31;
            float acc = 0.0f;
#pragma unroll
            for (int ky = 0; ky < 16; ky++) {
                float2 gv = Gs[u][ky];
                float2 w = ytabs[(ky << 5) + v];
                acc += gv.x * w.x - gv.y * w.y;
            }
            float y = acc * (2.0f / 1024.0f);
            int I = ((qx << 5) + u + 16) & 127;
            int J = ((qy << 5) + v + 16) & 127;
            int s2 = ((I >> 5) << 2) | (J >> 5);
            long off = ((long)(b * 16 + s2) * 128) * NP + ((I & 31) << 5) + (J & 31);
            dout[off + (long)(og * 16 + o) * NP] = y;
        }
        __syncthreads();
    }
}

// ---------------- launch ----------------
extern "C" void kernel_launch(void* const* d_in, const int* in_sizes, int n_in,
                              void* d_out, int out_size) {
    const float* seq    = (const float*)d_in[0];
    const float* qkv_wr = (const float*)d_in[1];
    const float* qkv_wi = (const float*)d_in[2];
    const float* out_wr = (const float*)d_in[3];
    const float* out_wi = (const float*)d_in[4];
    const float* cpb_w1 = (const float*)d_in[5];
    const float* cpb_b1 = (const float*)d_in[6];
    const float* cpb_w2 = (const float*)d_in[7];
    const float* amask  = (const float*)d_in[8];
    float* outp = (float*)d_out;

    const int FG_SMEM = (16 * 1028 + 16 * 258 * 2) * 4;  // 98816 B
    cudaFuncSetAttribute(k_fg, cudaFuncAttributeMaxDynamicSharedMemorySize, FG_SMEM);

    k_init<<<1, 512>>>();
    k_cpb<<<1, 256>>>(cpb_w1, cpb_b1, cpb_w2);
    k_wprep<<<dim3(384, 8), 256>>>(qkv_wr, qkv_wi, 0);
    k_wprep<<<dim3(128, 8), 256>>>(out_wr, out_wi, 1);

    k_fg<<<dim3(16, 128), 512, FG_SMEM>>>(seq);          // DFT + grams, one pass
    k_prepA<<<dim3(8, 1024), dim3(32, 8)>>>();

    k_gemm<768><<<dim3(6, 2, 256), 256>>>();             // -> Fqh, Fkh, Veff

    k_scores<<<dim3(16, 8), 256>>>(amask);
    k_av<<<dim3(16, 128), 256>>>();

    k_gemm<256><<<dim3(2, 2, 256), 256>>>();
    k_inv2<<<dim3(256, 8), 256>>>(outp);
}

// round 8
// speedup vs baseline: 1.1340x; 1.1340x over previous
#include <cuda_runtime.h>
#include <cuda_bf16.h>

#define NBS   256
#define NEMB  128
#define NP    1024
#define NMODE 256

#define S2f  1.41421356237f
#define IS2f 0.70710678119f

// ---------------- device scratch ----------------
__device__ float2 g_tw[32];
__device__ float2 g_ytab[512];
__device__ float  g_cpb[8 * 256];
__device__ float  g_attn[16 * 8 * 256];
__device__ float  g_gram[16 * 128 * 256];
__device__ float2 g_Xf [NBS * NEMB * NMODE];
__device__ __nv_bfloat16 g_Ab [256L * 256 * 2 * 256];          // A split [m][bs][h][re|im k]
__device__ __nv_bfloat16 g_Wqc[256L * 3 * 3 * 128 * 2 * 128];  // qkv W [m][oI][p:re,im,-im][n][h][k]
__device__ __nv_bfloat16 g_Woc[256L * 3 * 128 * 2 * 128];      // out W [m][p][n][h][k]
__device__ float  g_C2o[256L * 256 * 256];
__device__ __nv_bfloat16 g_Fqh[NBS * 512L * NEMB];
__device__ __nv_bfloat16 g_Fkh[NBS * 512L * NEMB];
__device__ float  g_VeR[NBS * NMODE * NEMB];
__device__ float  g_VeI[NBS * NMODE * NEMB];

__device__ __forceinline__ void bf_split(float v, __nv_bfloat16& h, __nv_bfloat16& l) {
    h = __float2bfloat16_rn(v);
    l = __float2bfloat16_rn(v - __bfloat162float(h));
}

__device__ __forceinline__ void cp16(unsigned dst, const void* src) {
    asm volatile("cp.async.ca.shared.global [%0], [%1], 16;" :: "r"(dst), "l"(src));
}
__device__ __forceinline__ void ldm_x4(unsigned& r0, unsigned& r1, unsigned& r2, unsigned& r3,
                                       unsigned addr) {
    asm volatile("ldmatrix.sync.aligned.m8n8.x4.shared.b16 {%0,%1,%2,%3}, [%4];"
                 : "=r"(r0), "=r"(r1), "=r"(r2), "=r"(r3) : "r"(addr));
}

// ---------------- init twiddles ----------------
__global__ void k_init() {
    int t = threadIdx.x;  // 512
    if (t < 32) {
        float s, c;
        sincospif((float)t * (1.0f / 16.0f), &s, &c);
        g_tw[t] = make_float2(c, s);
    }
    int ky = t >> 5, v = t & 31;
    float2 w;
    if (ky == 0) w = make_float2(0.5f, 0.0f);
    else { float s, c; sincospif((float)(ky * v) * (1.0f / 16.0f), &s, &c); w = make_float2(c, s); }
    g_ytab[t] = w;
}

// ---------------- log-CPB ----------------
__global__ void k_cpb(const float* __restrict__ w1, const float* __restrict__ b1,
                      const float* __restrict__ w2) {
    int t = threadIdx.x;
    int i = t >> 4, j = t & 15;
    float rx = (float)((i >> 2) - (j >> 2));
    float ry = (float)((i & 3) - (j & 3));
    float ax = log2f(1.0f + fabsf(rx)) * (8.0f / 3.0f);
    float ay = log2f(1.0f + fabsf(ry)) * (8.0f / 3.0f);
    ax = copysignf(ax, rx); ay = copysignf(ay, ry);
    float acc[8];
#pragma unroll
    for (int q = 0; q < 8; q++) acc[q] = 0.0f;
    for (int h = 0; h < 512; h++) {
        float hv = fmaxf(ax * w1[h] + ay * w1[512 + h] + b1[h], 0.0f);
#pragma unroll
        for (int q = 0; q < 8; q++) acc[q] += hv * w2[h * 8 + q];
    }
#pragma unroll
    for (int q = 0; q < 8; q++) g_cpb[(q * 16 + i) * 16 + j] = acc[q];
}

// ---------------- W prep: fold residual+mode weights, 3 sign planes ----------------
__global__ void k_wprep(const float* __restrict__ wr, const float* __restrict__ wi, int which) {
    int No = which ? 128 : 384;
    int o = blockIdx.x, m0 = blockIdx.y << 5;
    __shared__ float sr[128][33], si[128][33];
    int t = threadIdx.x;  // 256
    int mi = t & 31, c0 = t >> 5;
#pragma unroll
    for (int it = 0; it < 16; it++) {
        int c = (it << 3) + c0;
        long src = ((long)c * No + o) * 256 + m0 + mi;
        sr[c][mi] = wr[src];
        si[c][mi] = wi[src];
    }
    __syncthreads();
    int w = t >> 5, lane = t & 31;
    int oI = o >> 7, n = o & 127;
    const long PL = 32768;  // plane stride: 128*2*128
#pragma unroll
    for (int ml = 0; ml < 4; ml++) {
        int mi2 = (w << 2) + ml;
        long m = m0 + mi2;
        int ky = (int)(m & 15);
        float a, bco; int zim;
        if (which) { a = 0.0f; bco = 1.0f; zim = 0; }
        else if (oI == 2) {
            a = 1.0f; bco = (m == 0) ? 1.0f : ((ky == 0) ? 0.5f : 1.0f); zim = (m == 0);
        } else {
            if (m == 0)       { a = 1.0f;  bco = 1.0f;  zim = 1; }
            else if (ky == 0) { a = S2f;   bco = IS2f;  zim = 0; }
            else              { a = S2f;   bco = S2f;   zim = 0; }
        }
        long base = which ? (m * 3) * PL + (long)n * 256
                          : ((m * 3 + oI) * 3) * PL + (long)n * 256;
        __nv_bfloat16* dst = which ? g_Woc : g_Wqc;
#pragma unroll
        for (int kl = 0; kl < 4; kl++) {
            int k = (kl << 5) + lane;
            float vr = bco * sr[k][mi2] + ((k == n) ? a : 0.0f);
            if (which && k == n) vr = sr[k][mi2];
            float vi = zim ? 0.0f : bco * si[k][mi2];
            __nv_bfloat16 h, l;
            bf_split(vr, h, l);
            dst[base + k] = h;
            dst[base + 128 + k] = l;
            bf_split(vi, h, l);
            dst[base + PL + k] = h;
            dst[base + PL + 128 + k] = l;
            dst[base + 2 * PL + k] = __hneg(h);
            dst[base + 2 * PL + 128 + k] = __hneg(l);
        }
    }
}

// ---------------- fused: shift-gather + DFT(16 tokens) + spatial gram + freq gram ----------------
__global__ void __launch_bounds__(512) k_fg(const float* __restrict__ seq) {
    extern __shared__ float dyn[];
    float*  tiles = dyn;                              // 16 x 1028
    float2* sX    = (float2*)(dyn + 16 * 1028);       // 16 x 258
    __shared__ float2 T[16][33];
    __shared__ float2 tw[32];
    int b = blockIdx.x, c = blockIdx.y;
    int t = threadIdx.x;  // 512
    if (t < 32) tw[t] = g_tw[t];

#pragma unroll
    for (int k = 0; k < 32; k++) {
        int e = t + (k << 9);
        int s = e >> 10, p = e & 1023;
        int u = p >> 5, v = p & 31;
        int qx = s >> 2, qy = s & 3;
        int I = ((qx << 5) + u + 16) & 127;
        int J = ((qy << 5) + v + 16) & 127;
        int s2 = ((I >> 5) << 2) | (J >> 5);
        tiles[s * 1028 + p] = seq[(((b * 16 + s2) * 128 + c) * NP) + ((I & 31) << 5) + (J & 31)];
    }
    __syncthreads();

    for (int s = 0; s < 16; s++) {
        {
            int kx = t >> 5, v = t & 31;
            float tr = 0.0f, ti = 0.0f;
            int a = 0;
            const float* xs = tiles + s * 1028;
#pragma unroll
            for (int u = 0; u < 32; u++) {
                float x = xs[(u << 5) + v];
                float2 w = tw[a];
                tr += x * w.x; ti -= x * w.y;
                a = (a + kx) & 31;
            }
            T[kx][v] = make_float2(tr, ti);
        }
        __syncthreads();
        if (t < 256) {
            int kx = t >> 4, ky = t & 15;
            float xr = 0.0f, xi = 0.0f;
            int a = 0;
#pragma unroll
            for (int v = 0; v < 32; v++) {
                float2 tv = T[kx][v];
                float2 w = tw[a];
                xr += tv.x * w.x + tv.y * w.y;
                xi += tv.y * w.x - tv.x * w.y;
                a = (a + ky) & 31;
            }
            float2 X = make_float2(xr, xi);
            sX[s * 258 + t] = X;
            g_Xf[(long)((b * 16 + s) * 128 + c) * 256 + t] = X;
        }
        __syncthreads();
    }

    int ti = (t >> 2) & 3, tj = t & 3, g = t >> 4;
    float accS[4][4], accF[4][4];
#pragma unroll
    for (int ii = 0; ii < 4; ii++)
#pragma unroll
        for (int jj = 0; jj < 4; jj++) { accS[ii][jj] = 0.0f; accF[ii][jj] = 0.0f; }

#pragma unroll
    for (int w = 0; w < 32; w++) {
        int pl = (g << 5) + w;
        float av[4], bv[4];
#pragma unroll
        for (int ii = 0; ii < 4; ii++) av[ii] = tiles[(ti * 4 + ii) * 1028 + pl];
#pragma unroll
        for (int jj = 0; jj < 4; jj++) bv[jj] = tiles[(tj * 4 + jj) * 1028 + pl];
#pragma unroll
        for (int ii = 0; ii < 4; ii++)
#pragma unroll
            for (int jj = 0; jj < 4; jj++) accS[ii][jj] += av[ii] * bv[jj];
    }
#pragma unroll
    for (int mm = 0; mm < 8; mm++) {
        int m = (g << 3) + mm;
        float2 xv[4], yv[4];
#pragma unroll
        for (int ii = 0; ii < 4; ii++) xv[ii] = sX[(ti * 4 + ii) * 258 + m];
#pragma unroll
        for (int jj = 0; jj < 4; jj++) yv[jj] = sX[(tj * 4 + jj) * 258 + m];
#pragma unroll
        for (int ii = 0; ii < 4; ii++)
#pragma unroll
            for (int jj = 0; jj < 4; jj++)
                accF[ii][jj] += 2.0f * (xv[ii].x * yv[jj].x + xv[ii].y * yv[jj].y);
    }
    __syncthreads();
#pragma unroll
    for (int ii = 0; ii < 4; ii++)
#pragma unroll
        for (int jj = 0; jj < 4; jj++) {
            int pp = ((ti * 4 + ii) << 4) + tj * 4 + jj;
            tiles[pp * 33 + g] = accS[ii][jj] - accF[ii][jj] * (1.0f / 1024.0f);
        }
    __syncthreads();
    if (t < 256) {
        float ssum = 0.0f;
#pragma unroll
        for (int g2 = 0; g2 < 32; g2++) ssum += tiles[t * 33 + g2];
        int i = t >> 4, j = t & 15;
        ssum += sX[i * 258].x * sX[j * 258].x * (1.0f / 1024.0f);
        g_gram[(((b << 7) + c) << 8) + t] = ssum;
    }
}

// ---------------- A prep: transpose Xf -> realified split Ab ----------------
__global__ void k_prepA() {
    __shared__ float2 tile[32][33];
    int c0 = blockIdx.x << 5, r0 = blockIdx.y << 5;
    int tx = threadIdx.x, ty = threadIdx.y;
#pragma unroll
    for (int q = 0; q < 4; q++)
        tile[ty + (q << 3)][tx] = g_Xf[(long)(r0 + ty + (q << 3)) * 256 + c0 + tx];
    __syncthreads();
#pragma unroll
    for (int q = 0; q < 4; q++) {
        int m = c0 + ty + (q << 3);
        int row = r0 + tx;
        int bs = row >> 7, c = row & 127;
        float2 v = tile[tx][ty + (q << 3)];
        long base = ((long)m * 256 + bs) * 2 * 256;
        __nv_bfloat16 h, l;
        bf_split(v.x, h, l); g_Ab[base + c] = h;        g_Ab[base + 256 + c] = l;
        bf_split(v.y, h, l); g_Ab[base + 128 + c] = h;  g_Ab[base + 384 + c] = l;
    }
}

// ---------------- tensor-core GEMM: cp.async double-buffered, ldmatrix fragments ----------------
// dynamic smem: As[2][2][128][40] + Bs[2][2][128][40] bf16 = 81920 B
template <int NT>
__global__ void __launch_bounds__(256) k_gemm() {
    extern __shared__ __nv_bfloat16 smem[];
    const unsigned SM_A = (unsigned)__cvta_generic_to_shared(smem);
    const unsigned SM_B = SM_A + 40960;

    int nb = blockIdx.x, mb = blockIdx.y, mo = blockIdx.z;
    int t = threadIdx.x;
    int wid = t >> 5, lane = t & 31;
    int wm = wid & 1, wn = wid >> 1;
    int g = lane >> 2, tq = lane & 3;

    int isImOut = (NT == 768) ? (nb >= 3 ? 1 : 0) : nb;
    int oI      = (NT == 768) ? (nb - (isImOut ? 3 : 0)) : 0;
    const __nv_bfloat16* Wbase = (NT == 768)
        ? (g_Wqc + ((long)mo * 3 + oI) * 3 * 32768)
        : (g_Woc + (long)mo * 3 * 32768);
    const __nv_bfloat16* Abase = g_Ab + ((long)mo * 256 + mb * 128) * 512;

    int psel_re = isImOut ? 1 : 0;   // plane for k-real half
    int psel_im = isImOut ? 0 : 2;   // plane for k-imag half (2 = -im)

    float acc[4][4][4];
#pragma unroll
    for (int i = 0; i < 4; i++)
#pragma unroll
        for (int j = 0; j < 4; j++)
#pragma unroll
            for (int r = 0; r < 4; r++) acc[i][j][r] = 0.0f;

    int lr = t & 127, lh = t >> 7;
    // ldmatrix lane-address selectors
    int aRow = (lane & 7) + ((lane >> 3) & 1) * 8;   // 0..15
    int aK   = (lane >> 4) * 8;                       // 0 or 8
    int bRowOff = ((lane >> 4) << 3) + (lane & 7);    // within 16-n pair
    int bK   = ((lane >> 3) & 1) * 8;

    auto load_stage = [&](int buf, int k0) {
        unsigned da = SM_A + (unsigned)(((buf * 2 + lh) * 128 + lr) * 80);
        const __nv_bfloat16* sa = Abase + (long)lr * 512 + lh * 256 + k0;
        cp16(da, sa); cp16(da + 16, sa + 8); cp16(da + 32, sa + 16); cp16(da + 48, sa + 24);
        int p = (k0 >= 128) ? psel_im : psel_re;
        unsigned db = SM_B + (unsigned)(((buf * 2 + lh) * 128 + lr) * 80);
        const __nv_bfloat16* sb = Wbase + (long)p * 32768 + (long)lr * 256 + lh * 128 + (k0 & 127);
        cp16(db, sb); cp16(db + 16, sb + 8); cp16(db + 32, sb + 16); cp16(db + 48, sb + 24);
    };

    load_stage(0, 0);
    asm volatile("cp.async.commit_group;");

    for (int it = 0; it < 8; it++) {
        if (it < 7) {
            load_stage((it + 1) & 1, (it + 1) * 32);
            asm volatile("cp.async.commit_group;");
            asm volatile("cp.async.wait_group 1;");
        } else {
            asm volatile("cp.async.wait_group 0;");
        }
        __syncthreads();
        int buf = it & 1;
#pragma unroll
        for (int ks = 0; ks < 2; ks++) {
            int kb = ks * 16;
            unsigned ah[4][4], al[4][4], bh[4][2], bl[4][2];
#pragma unroll
            for (int mt = 0; mt < 4; mt++) {
                int row = wm * 64 + mt * 16 + aRow;
                int col = kb + aK;
                unsigned addr0 = SM_A + (unsigned)(((buf * 2 + 0) * 128 + row) * 80 + col * 2);
                unsigned addr1 = SM_A + (unsigned)(((buf * 2 + 1) * 128 + row) * 80 + col * 2);
                ldm_x4(ah[mt][0], ah[mt][1], ah[mt][2], ah[mt][3], addr0);
                ldm_x4(al[mt][0], al[mt][1], al[mt][2], al[mt][3], addr1);
            }
#pragma unroll
            for (int pr = 0; pr < 2; pr++) {
                int row = wn * 32 + pr * 16 + bRowOff;
                int col = kb + bK;
                unsigned addr0 = SM_B + (unsigned)(((buf * 2 + 0) * 128 + row) * 80 + col * 2);
                unsigned addr1 = SM_B + (unsigned)(((buf * 2 + 1) * 128 + row) * 80 + col * 2);
                ldm_x4(bh[2 * pr][0], bh[2 * pr][1], bh[2 * pr + 1][0], bh[2 * pr + 1][1], addr0);
                ldm_x4(bl[2 * pr][0], bl[2 * pr][1], bl[2 * pr + 1][0], bl[2 * pr + 1][1], addr1);
            }
#define MMA(d, a, b0, b1)                                                     \
    asm volatile("mma.sync.aligned.m16n8k16.row.col.f32.bf16.bf16.f32 "       \
                 "{%0,%1,%2,%3}, {%4,%5,%6,%7}, {%8,%9}, {%0,%1,%2,%3};"      \
                 : "+f"(d[0]), "+f"(d[1]), "+f"(d[2]), "+f"(d[3])             \
                 : "r"(a[0]), "r"(a[1]), "r"(a[2]), "r"(a[3]), "r"(b0), "r"(b1))
#pragma unroll
            for (int mt = 0; mt < 4; mt++)
#pragma unroll
                for (int nt = 0; nt < 4; nt++) {
                    MMA(acc[mt][nt], ah[mt], bh[nt][0], bh[nt][1]);
                    MMA(acc[mt][nt], ah[mt], bl[nt][0], bl[nt][1]);
                    MMA(acc[mt][nt], al[mt], bh[nt][0], bh[nt][1]);
                }
#undef MMA
        }
        __syncthreads();
    }

    if (NT == 768) {
#pragma unroll
        for (int mt = 0; mt < 4; mt++)
#pragma unroll
            for (int nt = 0; nt < 4; nt++) {
                int c = wn * 32 + nt * 8 + 2 * tq;
#pragma unroll
                for (int rr = 0; rr < 2; rr++) {
                    int bs = mb * 128 + wm * 64 + mt * 16 + g + rr * 8;
                    float2 val = make_float2(acc[mt][nt][rr * 2], acc[mt][nt][rr * 2 + 1]);
                    long fidx = (long)bs * 65536 + (2L * mo + isImOut) * 128 + c;
                    if (oI == 0)
                        *(__nv_bfloat162*)&g_Fqh[fidx] = __floats2bfloat162_rn(val.x, val.y);
                    else if (oI == 1)
                        *(__nv_bfloat162*)&g_Fkh[fidx] = __floats2bfloat162_rn(val.x, val.y);
                    else {
                        float* vp = isImOut ? g_VeI : g_VeR;
                        *(float2*)&vp[((long)bs * 256 + mo) * 128 + c] = val;
                    }
                }
            }
    } else {
#pragma unroll
        for (int mt = 0; mt < 4; mt++)
#pragma unroll
            for (int nt = 0; nt < 4; nt++) {
                int row = mb * 128 + wm * 64 + mt * 16 + g;
                long base = ((long)mo * 256 + row) * NT + nb * 128 + wn * 32 + nt * 8 + 2 * tq;
                *(float2*)&g_C2o[base] = make_float2(acc[mt][nt][0], acc[mt][nt][1]);
                *(float2*)&g_C2o[base + 8L * NT] = make_float2(acc[mt][nt][2], acc[mt][nt][3]);
            }
    }
}

// ---------------- scores + bias + softmax (bf16 features) ----------------
__global__ void k_scores(const float* __restrict__ amask) {
    int b = blockIdx.x, n = blockIdx.y;
    __shared__ float sq[16 * 132], sk[16 * 132];
    int t = threadIdx.x;
    int i = t >> 4, j = t & 15;
    float D = 0.0f;

    for (int ch = 0; ch < 64; ch++) {
#pragma unroll
        for (int k = 0; k < 4; k++) {
            int e = t + (k << 8);
            int dp = e & 7, mcL = (e >> 3) & 7, ii = e >> 6;
            long ga = ((long)((b << 4) + ii) * 512 + (ch << 3) + mcL) * 128 + (n << 4) + (dp << 1);
            int sa = ii * 132 + (mcL << 4) + (dp << 1);
            __nv_bfloat162 q2 = *(const __nv_bfloat162*)&g_Fqh[ga];
            __nv_bfloat162 k2 = *(const __nv_bfloat162*)&g_Fkh[ga];
            float2 qf = __bfloat1622float2(q2);
            float2 kf = __bfloat1622float2(k2);
            *(float2*)&sq[sa] = qf;
            *(float2*)&sk[sa] = kf;
        }
        __syncthreads();
        const float4* aq = (const float4*)(sq + i * 132);
        const float4* ak = (const float4*)(sk + j * 132);
#pragma unroll
        for (int r = 0; r < 32; r++) {
            float4 a = aq[r], bb = ak[r];
            D += a.x * bb.x + a.y * bb.y + a.z * bb.z + a.w * bb.w;
        }
        __syncthreads();
    }

    float gsum = 0.0f;
#pragma unroll
    for (int d = 0; d < 16; d++)
        gsum += g_gram[(((b << 7) + (n << 4) + d) << 8) + t];

    float s = (gsum + D * (1.0f / 1024.0f)) * (1.0f / 4096.0f);
    s += amask[(((b & 3) * 8 + n) << 8) + t] + g_cpb[(n << 8) + t];
    float mx = s;
#pragma unroll
    for (int off = 8; off; off >>= 1) mx = fmaxf(mx, __shfl_xor_sync(0xffffffffu, mx, off));
    float e = expf(s - mx);
    float su = e;
#pragma unroll
    for (int off = 8; off; off >>= 1) su += __shfl_xor_sync(0xffffffffu, su, off);
    g_attn[((b * 8 + n) << 8) + t] = e / su;
}

// ---------------- attn x Veff -> realified split A for out GEMM ----------------
__global__ void k_av() {
    int b = blockIdx.x, mch = blockIdx.y;
    __shared__ float2 sV[16][2][128];
    __shared__ float sA[2048];
    int t = threadIdx.x;
#pragma unroll
    for (int k = 0; k < 8; k++) sA[t + (k << 8)] = g_attn[b * 2048 + t + (k << 8)];
#pragma unroll
    for (int k = 0; k < 16; k++) {
        int e = t + (k << 8);
        int c = e & 127, mo = (e >> 7) & 1, j = e >> 8;
        long vi = ((long)((b << 4) + j) * 256 + (mch << 1) + mo) * 128 + c;
        sV[j][mo][c] = make_float2(g_VeR[vi], g_VeI[vi]);
    }
    __syncthreads();
    int c = t & 127, mo = t >> 7;
    int n = c >> 4;
    float2 acc[16];
#pragma unroll
    for (int ii = 0; ii < 16; ii++) acc[ii] = make_float2(0.0f, 0.0f);
#pragma unroll
    for (int jj = 0; jj < 16; jj++) {
        float2 v = sV[jj][mo][c];
#pragma unroll
        for (int ii = 0; ii < 16; ii++) {
            float a = sA[(n << 8) + (ii << 4) + jj];
            acc[ii].x += a * v.x;
            acc[ii].y += a * v.y;
        }
    }
    int m = (mch << 1) + mo;
#pragma unroll
    for (int ii = 0; ii < 16; ii++) {
        int bs = (b << 4) + ii;
        long base = ((long)m * 256 + bs) * 2 * 256;
        __nv_bfloat16 h, l;
        bf_split(acc[ii].x, h, l); g_Ab[base + c] = h;       g_Ab[base + 256 + c] = l;
        bf_split(acc[ii].y, h, l); g_Ab[base + 128 + c] = h; g_Ab[base + 384 + c] = l;
    }
}

// ---------------- inverse irfft2, 16 channels/block, direct C2o read, fused un-shift ----------------
__global__ void k_inv2(float* __restrict__ dout) {
    int bs = blockIdx.x, og = blockIdx.y;
    __shared__ float2 sS[16][257];
    __shared__ float2 Gs[32][17];
    __shared__ float2 ytabs[512];
    __shared__ float2 tw[32];
    int t = threadIdx.x;
    if (t < 32) tw[t] = g_tw[t];
    ytabs[t]       = g_ytab[t];
    ytabs[t + 256] = g_ytab[t + 256];
    {
        long base = (long)t * 65536 + bs * 256 + og * 16;
        float re[16], im[16];
#pragma unroll
        for (int q = 0; q < 4; q++) {
            *(float4*)&re[q * 4] = *(const float4*)&g_C2o[base + q * 4];
            *(float4*)&im[q * 4] = *(const float4*)&g_C2o[base + 128 + q * 4];
        }
#pragma unroll
        for (int ol = 0; ol < 16; ol++)
            sS[ol][t] = make_float2(re[ol], im[ol]);
    }
    __syncthreads();

    int b = bs >> 4, s = bs & 15, qx = s >> 2, qy = s & 3;
    for (int o = 0; o < 16; o++) {
#pragma unroll
        for (int q = 0; q < 2; q++) {
            int idx = t + (q << 8);
            int u = idx >> 4, ky = idx & 15;
            float gr = 0.0f, gi = 0.0f;
            int a = 0;
#pragma unroll
            for (int kx = 0; kx < 16; kx++) {
                float2 sv = sS[o][(kx << 4) + ky];
                float2 w = tw[a];
                gr += sv.x * w.x - sv.y * w.y;
                gi += sv.x * w.y + sv.y * w.x;
                a = (a + u) & 31;
            }
            Gs[u][ky] = make_float2(gr, gi);
        }
        __syncthreads();
#pragma unroll
        for (int q = 0; q < 4; q++) {
            int idx = t + (q << 8);
            int u = idx >> 5, v = idx & 31;
            float acc = 0.0f;
#pragma unroll
            for (int ky = 0; ky < 16; ky++) {
                float2 gv = Gs[u][ky];
                float2 w = ytabs[(ky << 5) + v];
                acc += gv.x * w.x - gv.y * w.y;
            }
            float y = acc * (2.0f / 1024.0f);
            int I = ((qx << 5) + u + 16) & 127;
            int J = ((qy << 5) + v + 16) & 127;
            int s2 = ((I >> 5) << 2) | (J >> 5);
            long off = ((long)(b * 16 + s2) * 128) * NP + ((I & 31) << 5) + (J & 31);
            dout[off + (long)(og * 16 + o) * NP] = y;
        }
        __syncthreads();
    }
}

// ---------------- launch ----------------
extern "C" void kernel_launch(void* const* d_in, const int* in_sizes, int n_in,
                              void* d_out, int out_size) {
    const float* seq    = (const float*)d_in[0];
    const float* qkv_wr = (const float*)d_in[1];
    const float* qkv_wi = (const float*)d_in[2];
    const float* out_wr = (const float*)d_in[3];
    const float* out_wi = (const float*)d_in[4];
    const float* cpb_w1 = (const float*)d_in[5];
    const float* cpb_b1 = (const float*)d_in[6];
    const float* cpb_w2 = (const float*)d_in[7];
    const float* amask  = (const float*)d_in[8];
    float* outp = (float*)d_out;

    const int FG_SMEM = (16 * 1028 + 16 * 258 * 2) * 4;  // 98816 B
    cudaFuncSetAttribute(k_fg, cudaFuncAttributeMaxDynamicSharedMemorySize, FG_SMEM);
    const int GEMM_SMEM = 81920;
    cudaFuncSetAttribute(k_gemm<768>, cudaFuncAttributeMaxDynamicSharedMemorySize, GEMM_SMEM);
    cudaFuncSetAttribute(k_gemm<256>, cudaFuncAttributeMaxDynamicSharedMemorySize, GEMM_SMEM);

    k_init<<<1, 512>>>();
    k_cpb<<<1, 256>>>(cpb_w1, cpb_b1, cpb_w2);
    k_wprep<<<dim3(384, 8), 256>>>(qkv_wr, qkv_wi, 0);
    k_wprep<<<dim3(128, 8), 256>>>(out_wr, out_wi, 1);

    k_fg<<<dim3(16, 128), 512, FG_SMEM>>>(seq);
    k_prepA<<<dim3(8, 1024), dim3(32, 8)>>>();

    k_gemm<768><<<dim3(6, 2, 256), 256, GEMM_SMEM>>>();

    k_scores<<<dim3(16, 8), 256>>>(amask);
    k_av<<<dim3(16, 128), 256>>>();

    k_gemm<256><<<dim3(2, 2, 256), 256, GEMM_SMEM>>>();
    k_inv2<<<dim3(256, 8), 256, 0>>>(outp);
}

// round 9
// speedup vs baseline: 1.3490x; 1.1897x over previous
#include <cuda_runtime.h>
#include <cuda_bf16.h>

#define NBS   256
#define NEMB  128
#define NP    1024
#define NMODE 256

#define S2f  1.41421356237f
#define IS2f 0.70710678119f

// ---------------- device scratch ----------------
__device__ float2 g_tw[32];
__device__ float2 g_ytab[512];
__device__ float  g_cpb[8 * 256];
__device__ float  g_attn[16 * 8 * 256];
__device__ float  g_gram[16 * 128 * 256];
__device__ float  g_Dpart[16 * 8 * 8 * 256];
__device__ float2 g_Xf [NBS * NEMB * NMODE];
__device__ __nv_bfloat16 g_Ab [256L * 256 * 2 * 256];          // A split [m][bs][h][re|im k]
__device__ __nv_bfloat16 g_Wqc[256L * 3 * 3 * 128 * 2 * 128];  // qkv W [m][oI][p:re,im,-im][n][h][k]
__device__ __nv_bfloat16 g_Woc[256L * 3 * 128 * 2 * 128];      // out W [m][p][n][h][k]
__device__ float  g_C2o[256L * 256 * 256];
__device__ __nv_bfloat16 g_Fqh[NBS * 512L * NEMB];
__device__ __nv_bfloat16 g_Fkh[NBS * 512L * NEMB];
__device__ float  g_VeR[NBS * NMODE * NEMB];
__device__ float  g_VeI[NBS * NMODE * NEMB];

__device__ __forceinline__ void bf_split(float v, __nv_bfloat16& h, __nv_bfloat16& l) {
    h = __float2bfloat16_rn(v);
    l = __float2bfloat16_rn(v - __bfloat162float(h));
}

__device__ __forceinline__ void cp16(unsigned dst, const void* src) {
    asm volatile("cp.async.ca.shared.global [%0], [%1], 16;" :: "r"(dst), "l"(src));
}
__device__ __forceinline__ void ldm_x4(unsigned& r0, unsigned& r1, unsigned& r2, unsigned& r3,
                                       unsigned addr) {
    asm volatile("ldmatrix.sync.aligned.m8n8.x4.shared.b16 {%0,%1,%2,%3}, [%4];"
                 : "=r"(r0), "=r"(r1), "=r"(r2), "=r"(r3) : "r"(addr));
}

// ---------------- init twiddles + log-CPB (merged, 2 blocks) ----------------
__global__ void k_init(const float* __restrict__ w1, const float* __restrict__ b1,
                       const float* __restrict__ w2) {
    int t = threadIdx.x;  // 512
    if (blockIdx.x == 0) {
        if (t < 32) {
            float s, c;
            sincospif((float)t * (1.0f / 16.0f), &s, &c);
            g_tw[t] = make_float2(c, s);
        }
        int ky = t >> 5, v = t & 31;
        float2 w;
        if (ky == 0) w = make_float2(0.5f, 0.0f);
        else { float s, c; sincospif((float)(ky * v) * (1.0f / 16.0f), &s, &c); w = make_float2(c, s); }
        g_ytab[t] = w;
    } else if (t < 256) {
        int i = t >> 4, j = t & 15;
        float rx = (float)((i >> 2) - (j >> 2));
        float ry = (float)((i & 3) - (j & 3));
        float ax = log2f(1.0f + fabsf(rx)) * (8.0f / 3.0f);
        float ay = log2f(1.0f + fabsf(ry)) * (8.0f / 3.0f);
        ax = copysignf(ax, rx); ay = copysignf(ay, ry);
        float acc[8];
#pragma unroll
        for (int q = 0; q < 8; q++) acc[q] = 0.0f;
        for (int h = 0; h < 512; h++) {
            float hv = fmaxf(ax * w1[h] + ay * w1[512 + h] + b1[h], 0.0f);
#pragma unroll
            for (int q = 0; q < 8; q++) acc[q] += hv * w2[h * 8 + q];
        }
#pragma unroll
        for (int q = 0; q < 8; q++) g_cpb[(q * 16 + i) * 16 + j] = acc[q];
    }
}

// ---------------- W prep: fold residual+mode weights, 3 sign planes ----------------
__global__ void k_wprep(const float* __restrict__ wr, const float* __restrict__ wi, int which) {
    int No = which ? 128 : 384;
    int o = blockIdx.x, m0 = blockIdx.y << 5;
    __shared__ float sr[128][33], si[128][33];
    int t = threadIdx.x;  // 256
    int mi = t & 31, c0 = t >> 5;
#pragma unroll
    for (int it = 0; it < 16; it++) {
        int c = (it << 3) + c0;
        long src = ((long)c * No + o) * 256 + m0 + mi;
        sr[c][mi] = wr[src];
        si[c][mi] = wi[src];
    }
    __syncthreads();
    int w = t >> 5, lane = t & 31;
    int oI = o >> 7, n = o & 127;
    const long PL = 32768;
#pragma unroll
    for (int ml = 0; ml < 4; ml++) {
        int mi2 = (w << 2) + ml;
        long m = m0 + mi2;
        int ky = (int)(m & 15);
        float a, bco; int zim;
        if (which) { a = 0.0f; bco = 1.0f; zim = 0; }
        else if (oI == 2) {
            a = 1.0f; bco = (m == 0) ? 1.0f : ((ky == 0) ? 0.5f : 1.0f); zim = (m == 0);
        } else {
            if (m == 0)       { a = 1.0f;  bco = 1.0f;  zim = 1; }
            else if (ky == 0) { a = S2f;   bco = IS2f;  zim = 0; }
            else              { a = S2f;   bco = S2f;   zim = 0; }
        }
        long base = which ? (m * 3) * PL + (long)n * 256
                          : ((m * 3 + oI) * 3) * PL + (long)n * 256;
        __nv_bfloat16* dst = which ? g_Woc : g_Wqc;
#pragma unroll
        for (int kl = 0; kl < 4; kl++) {
            int k = (kl << 5) + lane;
            float vr = bco * sr[k][mi2] + ((k == n) ? a : 0.0f);
            if (which && k == n) vr = sr[k][mi2];
            float vi = zim ? 0.0f : bco * si[k][mi2];
            __nv_bfloat16 h, l;
            bf_split(vr, h, l);
            dst[base + k] = h;
            dst[base + 128 + k] = l;
            bf_split(vi, h, l);
            dst[base + PL + k] = h;
            dst[base + PL + 128 + k] = l;
            dst[base + 2 * PL + k] = __hneg(h);
            dst[base + 2 * PL + 128 + k] = __hneg(l);
        }
    }
}

// ---------------- fused: shift-gather + batched DFT + spatial gram + freq gram ----------------
// dyn smem: tiles 16x1028 f32 + sX 16x258 float2 + Tall 16x16x33 float2 = 166400 B
__global__ void __launch_bounds__(512) k_fg(const float* __restrict__ seq) {
    extern __shared__ float dyn[];
    float*  tiles = dyn;                              // 16 x 1028
    float2* sX    = (float2*)(dyn + 16 * 1028);       // 16 x 258
    float2* Tall  = sX + 16 * 258;                    // [s][kx][v] : 16 x 16 x 33
    __shared__ float2 tw[32];
    int b = blockIdx.x, c = blockIdx.y;
    int t = threadIdx.x;  // 512
    if (t < 32) tw[t] = g_tw[t];

#pragma unroll
    for (int k = 0; k < 32; k++) {
        int e = t + (k << 9);
        int s = e >> 10, p = e & 1023;
        int u = p >> 5, v = p & 31;
        int qx = s >> 2, qy = s & 3;
        int I = ((qx << 5) + u + 16) & 127;
        int J = ((qy << 5) + v + 16) & 127;
        int s2 = ((I >> 5) << 2) | (J >> 5);
        tiles[s * 1028 + p] = seq[(((b * 16 + s2) * 128 + c) * NP) + ((I & 31) << 5) + (J & 31)];
    }
    __syncthreads();

    // stage 1 for all 16 tokens at once: thread -> (kx = t>>5, v = t&31)
    {
        int kx = t >> 5, v = t & 31;
        float tr[16], ti[16];
#pragma unroll
        for (int s = 0; s < 16; s++) { tr[s] = 0.0f; ti[s] = 0.0f; }
        int a = 0;
#pragma unroll
        for (int u = 0; u < 32; u++) {
            float2 w = tw[a];
#pragma unroll
            for (int s = 0; s < 16; s++) {
                float x = tiles[s * 1028 + (u << 5) + v];
                tr[s] += x * w.x;
                ti[s] -= x * w.y;
            }
            a = (a + kx) & 31;
        }
#pragma unroll
        for (int s = 0; s < 16; s++)
            Tall[(s * 16 + kx) * 33 + v] = make_float2(tr[s], ti[s]);
    }
    __syncthreads();

    // stage 2: thread handles (kx,ky) = t&255 for 8 tokens (half = t>>8)
    {
        int m = t & 255, half = t >> 8;
        int kx = m >> 4, ky = m & 15;
        float xr[8], xi[8];
#pragma unroll
        for (int sl = 0; sl < 8; sl++) { xr[sl] = 0.0f; xi[sl] = 0.0f; }
        int a = 0;
#pragma unroll
        for (int v = 0; v < 32; v++) {
            float2 w = tw[a];
#pragma unroll
            for (int sl = 0; sl < 8; sl++) {
                float2 tv = Tall[((half * 8 + sl) * 16 + kx) * 33 + v];
                xr[sl] += tv.x * w.x + tv.y * w.y;
                xi[sl] += tv.y * w.x - tv.x * w.y;
            }
            a = (a + ky) & 31;
        }
#pragma unroll
        for (int sl = 0; sl < 8; sl++) {
            int s = half * 8 + sl;
            float2 X = make_float2(xr[sl], xi[sl]);
            sX[s * 258 + m] = X;
            g_Xf[(long)((b * 16 + s) * 128 + c) * 256 + m] = X;
        }
    }
    __syncthreads();

    // grams
    int ti = (t >> 2) & 3, tj = t & 3, g = t >> 4;
    float accS[4][4], accF[4][4];
#pragma unroll
    for (int ii = 0; ii < 4; ii++)
#pragma unroll
        for (int jj = 0; jj < 4; jj++) { accS[ii][jj] = 0.0f; accF[ii][jj] = 0.0f; }

#pragma unroll
    for (int w = 0; w < 32; w++) {
        int pl = (g << 5) + w;
        float av[4], bv[4];
#pragma unroll
        for (int ii = 0; ii < 4; ii++) av[ii] = tiles[(ti * 4 + ii) * 1028 + pl];
#pragma unroll
        for (int jj = 0; jj < 4; jj++) bv[jj] = tiles[(tj * 4 + jj) * 1028 + pl];
#pragma unroll
        for (int ii = 0; ii < 4; ii++)
#pragma unroll
            for (int jj = 0; jj < 4; jj++) accS[ii][jj] += av[ii] * bv[jj];
    }
#pragma unroll
    for (int mm = 0; mm < 8; mm++) {
        int m = (g << 3) + mm;
        float2 xv[4], yv[4];
#pragma unroll
        for (int ii = 0; ii < 4; ii++) xv[ii] = sX[(ti * 4 + ii) * 258 + m];
#pragma unroll
        for (int jj = 0; jj < 4; jj++) yv[jj] = sX[(tj * 4 + jj) * 258 + m];
#pragma unroll
        for (int ii = 0; ii < 4; ii++)
#pragma unroll
            for (int jj = 0; jj < 4; jj++)
                accF[ii][jj] += 2.0f * (xv[ii].x * yv[jj].x + xv[ii].y * yv[jj].y);
    }
    __syncthreads();
#pragma unroll
    for (int ii = 0; ii < 4; ii++)
#pragma unroll
        for (int jj = 0; jj < 4; jj++) {
            int pp = ((ti * 4 + ii) << 4) + tj * 4 + jj;
            tiles[pp * 33 + g] = accS[ii][jj] - accF[ii][jj] * (1.0f / 1024.0f);
        }
    __syncthreads();
    if (t < 256) {
        float ssum = 0.0f;
#pragma unroll
        for (int g2 = 0; g2 < 32; g2++) ssum += tiles[t * 33 + g2];
        int i = t >> 4, j = t & 15;
        ssum += sX[i * 258].x * sX[j * 258].x * (1.0f / 1024.0f);
        g_gram[(((b << 7) + c) << 8) + t] = ssum;
    }
}

// ---------------- A prep: transpose Xf -> realified split Ab ----------------
__global__ void k_prepA() {
    __shared__ float2 tile[32][33];
    int c0 = blockIdx.x << 5, r0 = blockIdx.y << 5;
    int tx = threadIdx.x, ty = threadIdx.y;
#pragma unroll
    for (int q = 0; q < 4; q++)
        tile[ty + (q << 3)][tx] = g_Xf[(long)(r0 + ty + (q << 3)) * 256 + c0 + tx];
    __syncthreads();
#pragma unroll
    for (int q = 0; q < 4; q++) {
        int m = c0 + ty + (q << 3);
        int row = r0 + tx;
        int bs = row >> 7, c = row & 127;
        float2 v = tile[tx][ty + (q << 3)];
        long base = ((long)m * 256 + bs) * 2 * 256;
        __nv_bfloat16 h, l;
        bf_split(v.x, h, l); g_Ab[base + c] = h;        g_Ab[base + 256 + c] = l;
        bf_split(v.y, h, l); g_Ab[base + 128 + c] = h;  g_Ab[base + 384 + c] = l;
    }
}

// ---------------- tensor-core GEMM: cp.async double-buffered, ldmatrix fragments ----------------
template <int NT>
__global__ void __launch_bounds__(256) k_gemm() {
    extern __shared__ __nv_bfloat16 smem[];
    const unsigned SM_A = (unsigned)__cvta_generic_to_shared(smem);
    const unsigned SM_B = SM_A + 40960;

    int nb = blockIdx.x, mb = blockIdx.y, mo = blockIdx.z;
    int t = threadIdx.x;
    int wid = t >> 5, lane = t & 31;
    int wm = wid & 1, wn = wid >> 1;
    int g = lane >> 2, tq = lane & 3;

    int isImOut = (NT == 768) ? (nb >= 3 ? 1 : 0) : nb;
    int oI      = (NT == 768) ? (nb - (isImOut ? 3 : 0)) : 0;
    const __nv_bfloat16* Wbase = (NT == 768)
        ? (g_Wqc + ((long)mo * 3 + oI) * 3 * 32768)
        : (g_Woc + (long)mo * 3 * 32768);
    const __nv_bfloat16* Abase = g_Ab + ((long)mo * 256 + mb * 128) * 512;

    int psel_re = isImOut ? 1 : 0;
    int psel_im = isImOut ? 0 : 2;

    float acc[4][4][4];
#pragma unroll
    for (int i = 0; i < 4; i++)
#pragma unroll
        for (int j = 0; j < 4; j++)
#pragma unroll
            for (int r = 0; r < 4; r++) acc[i][j][r] = 0.0f;

    int lr = t & 127, lh = t >> 7;
    int aRow = (lane & 7) + ((lane >> 3) & 1) * 8;
    int aK   = (lane >> 4) * 8;
    int bRowOff = ((lane >> 4) << 3) + (lane & 7);
    int bK   = ((lane >> 3) & 1) * 8;

    auto load_stage = [&](int buf, int k0) {
        unsigned da = SM_A + (unsigned)(((buf * 2 + lh) * 128 + lr) * 80);
        const __nv_bfloat16* sa = Abase + (long)lr * 512 + lh * 256 + k0;
        cp16(da, sa); cp16(da + 16, sa + 8); cp16(da + 32, sa + 16); cp16(da + 48, sa + 24);
        int p = (k0 >= 128) ? psel_im : psel_re;
        unsigned db = SM_B + (unsigned)(((buf * 2 + lh) * 128 + lr) * 80);
        const __nv_bfloat16* sb = Wbase + (long)p * 32768 + (long)lr * 256 + lh * 128 + (k0 & 127);
        cp16(db, sb); cp16(db + 16, sb + 8); cp16(db + 32, sb + 16); cp16(db + 48, sb + 24);
    };

    load_stage(0, 0);
    asm volatile("cp.async.commit_group;");

    for (int it = 0; it < 8; it++) {
        if (it < 7) {
            load_stage((it + 1) & 1, (it + 1) * 32);
            asm volatile("cp.async.commit_group;");
            asm volatile("cp.async.wait_group 1;");
        } else {
            asm volatile("cp.async.wait_group 0;");
        }
        __syncthreads();
        int buf = it & 1;
#pragma unroll
        for (int ks = 0; ks < 2; ks++) {
            int kb = ks * 16;
            unsigned ah[4][4], al[4][4], bh[4][2], bl[4][2];
#pragma unroll
            for (int mt = 0; mt < 4; mt++) {
                int row = wm * 64 + mt * 16 + aRow;
                int col = kb + aK;
                unsigned addr0 = SM_A + (unsigned)(((buf * 2 + 0) * 128 + row) * 80 + col * 2);
                unsigned addr1 = SM_A + (unsigned)(((buf * 2 + 1) * 128 + row) * 80 + col * 2);
                ldm_x4(ah[mt][0], ah[mt][1], ah[mt][2], ah[mt][3], addr0);
                ldm_x4(al[mt][0], al[mt][1], al[mt][2], al[mt][3], addr1);
            }
#pragma unroll
            for (int pr = 0; pr < 2; pr++) {
                int row = wn * 32 + pr * 16 + bRowOff;
                int col = kb + bK;
                unsigned addr0 = SM_B + (unsigned)(((buf * 2 + 0) * 128 + row) * 80 + col * 2);
                unsigned addr1 = SM_B + (unsigned)(((buf * 2 + 1) * 128 + row) * 80 + col * 2);
                ldm_x4(bh[2 * pr][0], bh[2 * pr][1], bh[2 * pr + 1][0], bh[2 * pr + 1][1], addr0);
                ldm_x4(bl[2 * pr][0], bl[2 * pr][1], bl[2 * pr + 1][0], bl[2 * pr + 1][1], addr1);
            }
#define MMA(d, a, b0, b1)                                                     \
    asm volatile("mma.sync.aligned.m16n8k16.row.col.f32.bf16.bf16.f32 "       \
                 "{%0,%1,%2,%3}, {%4,%5,%6,%7}, {%8,%9}, {%0,%1,%2,%3};"      \
                 : "+f"(d[0]), "+f"(d[1]), "+f"(d[2]), "+f"(d[3])             \
                 : "r"(a[0]), "r"(a[1]), "r"(a[2]), "r"(a[3]), "r"(b0), "r"(b1))
#pragma unroll
            for (int mt = 0; mt < 4; mt++)
#pragma unroll
                for (int nt = 0; nt < 4; nt++) {
                    MMA(acc[mt][nt], ah[mt], bh[nt][0], bh[nt][1]);
                    MMA(acc[mt][nt], ah[mt], bl[nt][0], bl[nt][1]);
                    MMA(acc[mt][nt], al[mt], bh[nt][0], bh[nt][1]);
                }
#undef MMA
        }
        __syncthreads();
    }

    if (NT == 768) {
#pragma unroll
        for (int mt = 0; mt < 4; mt++)
#pragma unroll
            for (int nt = 0; nt < 4; nt++) {
                int c = wn * 32 + nt * 8 + 2 * tq;
#pragma unroll
                for (int rr = 0; rr < 2; rr++) {
                    int bs = mb * 128 + wm * 64 + mt * 16 + g + rr * 8;
                    float2 val = make_float2(acc[mt][nt][rr * 2], acc[mt][nt][rr * 2 + 1]);
                    long fidx = (long)bs * 65536 + (2L * mo + isImOut) * 128 + c;
                    if (oI == 0)
                        *(__nv_bfloat162*)&g_Fqh[fidx] = __floats2bfloat162_rn(val.x, val.y);
                    else if (oI == 1)
                        *(__nv_bfloat162*)&g_Fkh[fidx] = __floats2bfloat162_rn(val.x, val.y);
                    else {
                        float* vp = isImOut ? g_VeI : g_VeR;
                        *(float2*)&vp[((long)bs * 256 + mo) * 128 + c] = val;
                    }
                }
            }
    } else {
#pragma unroll
        for (int mt = 0; mt < 4; mt++)
#pragma unroll
            for (int nt = 0; nt < 4; nt++) {
                int row = mb * 128 + wm * 64 + mt * 16 + g;
                long base = ((long)mo * 256 + row) * NT + nb * 128 + wn * 32 + nt * 8 + 2 * tq;
                *(float2*)&g_C2o[base] = make_float2(acc[mt][nt][0], acc[mt][nt][1]);
                *(float2*)&g_C2o[base + 8L * NT] = make_float2(acc[mt][nt][2], acc[mt][nt][3]);
            }
    }
}

// ---------------- scores: partial feature-Gram (8x more CTAs) ----------------
__global__ void k_scores_part() {
    int b = blockIdx.x, n = blockIdx.y, pt = blockIdx.z;
    __shared__ float sq[16 * 132], sk[16 * 132];
    int t = threadIdx.x;
    int i = t >> 4, j = t & 15;
    float D = 0.0f;

    for (int ch0 = 0; ch0 < 8; ch0++) {
        int ch = pt * 8 + ch0;
#pragma unroll
        for (int k = 0; k < 4; k++) {
            int e = t + (k << 8);
            int dp = e & 7, mcL = (e >> 3) & 7, ii = e >> 6;
            long ga = ((long)((b << 4) + ii) * 512 + (ch << 3) + mcL) * 128 + (n << 4) + (dp << 1);
            int sa = ii * 132 + (mcL << 4) + (dp << 1);
            __nv_bfloat162 q2 = *(const __nv_bfloat162*)&g_Fqh[ga];
            __nv_bfloat162 k2 = *(const __nv_bfloat162*)&g_Fkh[ga];
            *(float2*)&sq[sa] = __bfloat1622float2(q2);
            *(float2*)&sk[sa] = __bfloat1622float2(k2);
        }
        __syncthreads();
        const float4* aq = (const float4*)(sq + i * 132);
        const float4* ak = (const float4*)(sk + j * 132);
#pragma unroll
        for (int r = 0; r < 32; r++) {
            float4 a = aq[r], bb = ak[r];
            D += a.x * bb.x + a.y * bb.y + a.z * bb.z + a.w * bb.w;
        }
        __syncthreads();
    }
    g_Dpart[(((b * 8 + n) * 8 + pt) << 8) + t] = D;
}

// ---------------- scores finalize: reduce partials + bias + softmax ----------------
__global__ void k_scores_fin(const float* __restrict__ amask) {
    int b = blockIdx.x, n = blockIdx.y;
    int t = threadIdx.x;
    float D = 0.0f;
#pragma unroll
    for (int p = 0; p < 8; p++)
        D += g_Dpart[(((b * 8 + n) * 8 + p) << 8) + t];

    float gsum = 0.0f;
#pragma unroll
    for (int d = 0; d < 16; d++)
        gsum += g_gram[(((b << 7) + (n << 4) + d) << 8) + t];

    float s = (gsum + D * (1.0f / 1024.0f)) * (1.0f / 4096.0f);
    s += amask[(((b & 3) * 8 + n) << 8) + t] + g_cpb[(n << 8) + t];
    float mx = s;
#pragma unroll
    for (int off = 8; off; off >>= 1) mx = fmaxf(mx, __shfl_xor_sync(0xffffffffu, mx, off));
    float e = expf(s - mx);
    float su = e;
#pragma unroll
    for (int off = 8; off; off >>= 1) su += __shfl_xor_sync(0xffffffffu, su, off);
    g_attn[((b * 8 + n) << 8) + t] = e / su;
}

// ---------------- attn x Veff -> realified split A for out GEMM ----------------
__global__ void k_av() {
    int b = blockIdx.x, mch = blockIdx.y;
    __shared__ float2 sV[16][2][128];
    __shared__ float sA[2048];
    int t = threadIdx.x;
#pragma unroll
    for (int k = 0; k < 8; k++) sA[t + (k << 8)] = g_attn[b * 2048 + t + (k << 8)];
#pragma unroll
    for (int k = 0; k < 16; k++) {
        int e = t + (k << 8);
        int c = e & 127, mo = (e >> 7) & 1, j = e >> 8;
        long vi = ((long)((b << 4) + j) * 256 + (mch << 1) + mo) * 128 + c;
        sV[j][mo][c] = make_float2(g_VeR[vi], g_VeI[vi]);
    }
    __syncthreads();
    int c = t & 127, mo = t >> 7;
    int n = c >> 4;
    float2 acc[16];
#pragma unroll
    for (int ii = 0; ii < 16; ii++) acc[ii] = make_float2(0.0f, 0.0f);
#pragma unroll
    for (int jj = 0; jj < 16; jj++) {
        float2 v = sV[jj][mo][c];
#pragma unroll
        for (int ii = 0; ii < 16; ii++) {
            float a = sA[(n << 8) + (ii << 4) + jj];
            acc[ii].x += a * v.x;
            acc[ii].y += a * v.y;
        }
    }
    int m = (mch << 1) + mo;
#pragma unroll
    for (int ii = 0; ii < 16; ii++) {
        int bs = (b << 4) + ii;
        long base = ((long)m * 256 + bs) * 2 * 256;
        __nv_bfloat16 h, l;
        bf_split(acc[ii].x, h, l); g_Ab[base + c] = h;       g_Ab[base + 256 + c] = l;
        bf_split(acc[ii].y, h, l); g_Ab[base + 128 + c] = h; g_Ab[base + 384 + c] = l;
    }
}

// ---------------- inverse irfft2, 8 channels/block, direct C2o read, fused un-shift ----------------
__global__ void k_inv2(float* __restrict__ dout) {
    int bs = blockIdx.x, og = blockIdx.y;     // og: 16 groups of 8 channels
    __shared__ float2 sS[8][257];
    __shared__ float2 Gs[32][17];
    __shared__ float2 ytabs[512];
    __shared__ float2 tw[32];
    int t = threadIdx.x;                      // 256
    if (t < 32) tw[t] = g_tw[t];
    ytabs[t]       = g_ytab[t];
    ytabs[t + 256] = g_ytab[t + 256];
    {
        long base = (long)t * 65536 + bs * 256 + og * 8;   // t = mode
        float re[8], im[8];
#pragma unroll
        for (int q = 0; q < 2; q++) {
            *(float4*)&re[q * 4] = *(const float4*)&g_C2o[base + q * 4];
            *(float4*)&im[q * 4] = *(const float4*)&g_C2o[base + 128 + q * 4];
        }
#pragma unroll
        for (int ol = 0; ol < 8; ol++)
            sS[ol][t] = make_float2(re[ol], im[ol]);
    }
    __syncthreads();

    int b = bs >> 4, s = bs & 15, qx = s >> 2, qy = s & 3;
    for (int o = 0; o < 8; o++) {
#pragma unroll
        for (int q = 0; q < 2; q++) {
            int idx = t + (q << 8);
            int u = idx >> 4, ky = idx & 15;
            float gr = 0.0f, gi = 0.0f;
            int a = 0;
#pragma unroll
            for (int kx = 0; kx < 16; kx++) {
                float2 sv = sS[o][(kx << 4) + ky];
                float2 w = tw[a];
                gr += sv.x * w.x - sv.y * w.y;
                gi += sv.x * w.y + sv.y * w.x;
                a = (a + u) & 31;
            }
            Gs[u][ky] = make_float2(gr, gi);
        }
        __syncthreads();
#pragma unroll
        for (int q = 0; q < 4; q++) {
            int idx = t + (q << 8);
            int u = idx >> 5, v = idx & 31;
            float acc = 0.0f;
#pragma unroll
            for (int ky = 0; ky < 16; ky++) {
                float2 gv = Gs[u][ky];
                float2 w = ytabs[(ky << 5) + v];
                acc += gv.x * w.x - gv.y * w.y;
            }
            float y = acc * (2.0f / 1024.0f);
            int I = ((qx << 5) + u + 16) & 127;
            int J = ((qy << 5) + v + 16) & 127;
            int s2 = ((I >> 5) << 2) | (J >> 5);
            long off = ((long)(b * 16 + s2) * 128) * NP + ((I & 31) << 5) + (J & 31);
            dout[off + (long)(og * 8 + o) * NP] = y;
        }
        __syncthreads();
    }
}

// ---------------- launch ----------------
extern "C" void kernel_launch(void* const* d_in, const int* in_sizes, int n_in,
                              void* d_out, int out_size) {
    const float* seq    = (const float*)d_in[0];
    const float* qkv_wr = (const float*)d_in[1];
    const float* qkv_wi = (const float*)d_in[2];
    const float* out_wr = (const float*)d_in[3];
    const float* out_wi = (const float*)d_in[4];
    const float* cpb_w1 = (const float*)d_in[5];
    const float* cpb_b1 = (const float*)d_in[6];
    const float* cpb_w2 = (const float*)d_in[7];
    const float* amask  = (const float*)d_in[8];
    float* outp = (float*)d_out;

    const int FG_SMEM = 16 * 1028 * 4 + 16 * 258 * 8 + 16 * 16 * 33 * 8;  // 166400 B
    cudaFuncSetAttribute(k_fg, cudaFuncAttributeMaxDynamicSharedMemorySize, FG_SMEM);
    const int GEMM_SMEM = 81920;
    cudaFuncSetAttribute(k_gemm<768>, cudaFuncAttributeMaxDynamicSharedMemorySize, GEMM_SMEM);
    cudaFuncSetAttribute(k_gemm<256>, cudaFuncAttributeMaxDynamicSharedMemorySize, GEMM_SMEM);

    k_init<<<2, 512>>>(cpb_w1, cpb_b1, cpb_w2);
    k_wprep<<<dim3(384, 8), 256>>>(qkv_wr, qkv_wi, 0);
    k_wprep<<<dim3(128, 8), 256>>>(out_wr, out_wi, 1);

    k_fg<<<dim3(16, 128), 512, FG_SMEM>>>(seq);
    k_prepA<<<dim3(8, 1024), dim3(32, 8)>>>();

    k_gemm<768><<<dim3(6, 2, 256), 256, GEMM_SMEM>>>();

    k_scores_part<<<dim3(16, 8, 8), 256>>>();
    k_scores_fin<<<dim3(16, 8), 256>>>(amask);
    k_av<<<dim3(16, 128), 256>>>();

    k_gemm<256><<<dim3(2, 2, 256), 256, GEMM_SMEM>>>();
    k_inv2<<<dim3(256, 16), 256>>>(outp);
}

// round 10
// speedup vs baseline: 1.3731x; 1.0178x over previous
#include <cuda_runtime.h>
#include <cuda_bf16.h>

#define NBS   256
#define NEMB  128
#define NP    1024
#define NMODE 256

#define S2f  1.41421356237f
#define IS2f 0.70710678119f

// ---------------- device scratch ----------------
__device__ float2 g_tw[32];
__device__ float2 g_ytab[512];
__device__ float  g_cpb[8 * 256];
__device__ float  g_attn[16 * 8 * 256];
__device__ float  g_gram[16 * 128 * 256];
__device__ float  g_Dpart[16 * 8 * 8 * 256];
__device__ float2 g_Xf [NBS * NEMB * NMODE];
__device__ __nv_bfloat16 g_Ab [256L * 256 * 2 * 256];          // A split [m][bs][h][re|im k]
__device__ __nv_bfloat16 g_Wqc[256L * 3 * 2 * 128 * 2 * 128];  // qkv W [m][oI][p:re,im][n][h][k]
__device__ __nv_bfloat16 g_Woc[256L * 2 * 128 * 2 * 128];      // out W [m][p][n][h][k]
__device__ float  g_C2o[256L * 256 * 256];
__device__ __nv_bfloat16 g_Fqh[NBS * 512L * NEMB];
__device__ __nv_bfloat16 g_Fkh[NBS * 512L * NEMB];
__device__ float  g_VeR[NBS * NMODE * NEMB];
__device__ float  g_VeI[NBS * NMODE * NEMB];

__device__ __forceinline__ void bf_split(float v, __nv_bfloat16& h, __nv_bfloat16& l) {
    h = __float2bfloat16_rn(v);
    l = __float2bfloat16_rn(v - __bfloat162float(h));
}

__device__ __forceinline__ void cp16(unsigned dst, const void* src) {
    asm volatile("cp.async.ca.shared.global [%0], [%1], 16;" :: "r"(dst), "l"(src));
}
__device__ __forceinline__ void ldm_x4(unsigned& r0, unsigned& r1, unsigned& r2, unsigned& r3,
                                       unsigned addr) {
    asm volatile("ldmatrix.sync.aligned.m8n8.x4.shared.b16 {%0,%1,%2,%3}, [%4];"
                 : "=r"(r0), "=r"(r1), "=r"(r2), "=r"(r3) : "r"(addr));
}

// ---------------- init twiddles + log-CPB (merged, 2 blocks) ----------------
__global__ void k_init(const float* __restrict__ w1, const float* __restrict__ b1,
                       const float* __restrict__ w2) {
    int t = threadIdx.x;  // 512
    if (blockIdx.x == 0) {
        if (t < 32) {
            float s, c;
            sincospif((float)t * (1.0f / 16.0f), &s, &c);
            g_tw[t] = make_float2(c, s);
        }
        int ky = t >> 5, v = t & 31;
        float2 w;
        if (ky == 0) w = make_float2(0.5f, 0.0f);
        else { float s, c; sincospif((float)(ky * v) * (1.0f / 16.0f), &s, &c); w = make_float2(c, s); }
        g_ytab[t] = w;
    } else if (t < 256) {
        int i = t >> 4, j = t & 15;
        float rx = (float)((i >> 2) - (j >> 2));
        float ry = (float)((i & 3) - (j & 3));
        float ax = log2f(1.0f + fabsf(rx)) * (8.0f / 3.0f);
        float ay = log2f(1.0f + fabsf(ry)) * (8.0f / 3.0f);
        ax = copysignf(ax, rx); ay = copysignf(ay, ry);
        float acc[8];
#pragma unroll
        for (int q = 0; q < 8; q++) acc[q] = 0.0f;
        for (int h = 0; h < 512; h++) {
            float hv = fmaxf(ax * w1[h] + ay * w1[512 + h] + b1[h], 0.0f);
#pragma unroll
            for (int q = 0; q < 8; q++) acc[q] += hv * w2[h * 8 + q];
        }
#pragma unroll
        for (int q = 0; q < 8; q++) g_cpb[(q * 16 + i) * 16 + j] = acc[q];
    }
}

// ---------------- W prep: fold residual+mode weights, 2 planes (re, im) ----------------
__global__ void k_wprep(const float* __restrict__ wr, const float* __restrict__ wi, int which) {
    int No = which ? 128 : 384;
    int o = blockIdx.x, m0 = blockIdx.y << 5;
    __shared__ float sr[128][33], si[128][33];
    int t = threadIdx.x;  // 256
    int mi = t & 31, c0 = t >> 5;
#pragma unroll
    for (int it = 0; it < 16; it++) {
        int c = (it << 3) + c0;
        long src = ((long)c * No + o) * 256 + m0 + mi;
        sr[c][mi] = wr[src];
        si[c][mi] = wi[src];
    }
    __syncthreads();
    int w = t >> 5, lane = t & 31;
    int oI = o >> 7, n = o & 127;
    const long PL = 32768;
#pragma unroll
    for (int ml = 0; ml < 4; ml++) {
        int mi2 = (w << 2) + ml;
        long m = m0 + mi2;
        int ky = (int)(m & 15);
        float a, bco; int zim;
        if (which) { a = 0.0f; bco = 1.0f; zim = 0; }
        else if (oI == 2) {
            a = 1.0f; bco = (m == 0) ? 1.0f : ((ky == 0) ? 0.5f : 1.0f); zim = (m == 0);
        } else {
            if (m == 0)       { a = 1.0f;  bco = 1.0f;  zim = 1; }
            else if (ky == 0) { a = S2f;   bco = IS2f;  zim = 0; }
            else              { a = S2f;   bco = S2f;   zim = 0; }
        }
        long base = which ? (m * 2) * PL + (long)n * 256
                          : ((m * 3 + oI) * 2) * PL + (long)n * 256;
        __nv_bfloat16* dst = which ? g_Woc : g_Wqc;
#pragma unroll
        for (int kl = 0; kl < 4; kl++) {
            int k = (kl << 5) + lane;
            float vr = bco * sr[k][mi2] + ((k == n) ? a : 0.0f);
            if (which && k == n) vr = sr[k][mi2];
            float vi = zim ? 0.0f : bco * si[k][mi2];
            __nv_bfloat16 h, l;
            bf_split(vr, h, l);
            dst[base + k] = h;
            dst[base + 128 + k] = l;
            bf_split(vi, h, l);
            dst[base + PL + k] = h;
            dst[base + PL + 128 + k] = l;
        }
    }
}

// ---------------- fused: shift-gather + batched DFT + spatial gram + freq gram ----------------
// dyn smem: tiles 16x1028 f32 + sX 16x258 float2 + Tall 16x16x33 float2 = 166400 B
__global__ void __launch_bounds__(512) k_fg(const float* __restrict__ seq) {
    extern __shared__ float dyn[];
    float*  tiles = dyn;                              // 16 x 1028
    float2* sX    = (float2*)(dyn + 16 * 1028);       // 16 x 258
    float2* Tall  = sX + 16 * 258;                    // [s][kx][v] : 16 x 16 x 33
    __shared__ float2 tw[32];
    int b = blockIdx.x, c = blockIdx.y;
    int t = threadIdx.x;  // 512
    if (t < 32) tw[t] = g_tw[t];

#pragma unroll
    for (int k = 0; k < 32; k++) {
        int e = t + (k << 9);
        int s = e >> 10, p = e & 1023;
        int u = p >> 5, v = p & 31;
        int qx = s >> 2, qy = s & 3;
        int I = ((qx << 5) + u + 16) & 127;
        int J = ((qy << 5) + v + 16) & 127;
        int s2 = ((I >> 5) << 2) | (J >> 5);
        tiles[s * 1028 + p] = seq[(((b * 16 + s2) * 128 + c) * NP) + ((I & 31) << 5) + (J & 31)];
    }
    __syncthreads();

    // stage 1: thread = (kxp = t>>6, half = (t>>5)&1, v = t&31); 2 kx x 8 tokens per thread
    {
        int kxp = t >> 6, half = (t >> 5) & 1, v = t & 31;
        int kx0 = kxp * 2, kx1 = kx0 + 1;
        float tr0[8], ti0[8], tr1[8], ti1[8];
#pragma unroll
        for (int sl = 0; sl < 8; sl++) { tr0[sl] = 0.0f; ti0[sl] = 0.0f; tr1[sl] = 0.0f; ti1[sl] = 0.0f; }
        int a0 = 0, a1 = 0;
#pragma unroll
        for (int u = 0; u < 32; u++) {
            float2 w0 = tw[a0], w1 = tw[a1];
#pragma unroll
            for (int sl = 0; sl < 8; sl++) {
                float x = tiles[(half * 8 + sl) * 1028 + (u << 5) + v];
                tr0[sl] += x * w0.x; ti0[sl] -= x * w0.y;
                tr1[sl] += x * w1.x; ti1[sl] -= x * w1.y;
            }
            a0 = (a0 + kx0) & 31; a1 = (a1 + kx1) & 31;
        }
#pragma unroll
        for (int sl = 0; sl < 8; sl++) {
            int s = half * 8 + sl;
            Tall[(s * 16 + kx0) * 33 + v] = make_float2(tr0[sl], ti0[sl]);
            Tall[(s * 16 + kx1) * 33 + v] = make_float2(tr1[sl], ti1[sl]);
        }
    }
    __syncthreads();

    // stage 2: thread = (q = t>>7 token quarter, kx = (t&127)>>3, kyp = t&7); 2 ky x 4 tokens
    {
        int q = t >> 7, mp = t & 127;
        int kx = mp >> 3, kyp = mp & 7;
        int ky0 = kyp * 2, ky1 = ky0 + 1;
        float xr0[4], xi0[4], xr1[4], xi1[4];
#pragma unroll
        for (int sl = 0; sl < 4; sl++) { xr0[sl] = 0.0f; xi0[sl] = 0.0f; xr1[sl] = 0.0f; xi1[sl] = 0.0f; }
        int a0 = 0, a1 = 0;
#pragma unroll
        for (int v = 0; v < 32; v++) {
            float2 w0 = tw[a0], w1 = tw[a1];
#pragma unroll
            for (int sl = 0; sl < 4; sl++) {
                float2 tv = Tall[((q * 4 + sl) * 16 + kx) * 33 + v];
                xr0[sl] += tv.x * w0.x + tv.y * w0.y;
                xi0[sl] += tv.y * w0.x - tv.x * w0.y;
                xr1[sl] += tv.x * w1.x + tv.y * w1.y;
                xi1[sl] += tv.y * w1.x - tv.x * w1.y;
            }
            a0 = (a0 + ky0) & 31; a1 = (a1 + ky1) & 31;
        }
#pragma unroll
        for (int sl = 0; sl < 4; sl++) {
            int s = q * 4 + sl;
            int m0 = (kx << 4) + ky0;
            sX[s * 258 + m0]     = make_float2(xr0[sl], xi0[sl]);
            sX[s * 258 + m0 + 1] = make_float2(xr1[sl], xi1[sl]);
            float4 pack = make_float4(xr0[sl], xi0[sl], xr1[sl], xi1[sl]);
            *(float4*)&g_Xf[(long)((b * 16 + s) * 128 + c) * 256 + m0] = pack;
        }
    }
    __syncthreads();

    // grams
    int ti = (t >> 2) & 3, tj = t & 3, g = t >> 4;
    float accS[4][4], accF[4][4];
#pragma unroll
    for (int ii = 0; ii < 4; ii++)
#pragma unroll
        for (int jj = 0; jj < 4; jj++) { accS[ii][jj] = 0.0f; accF[ii][jj] = 0.0f; }

#pragma unroll
    for (int w = 0; w < 32; w++) {
        int pl = (g << 5) + w;
        float av[4], bv[4];
#pragma unroll
        for (int ii = 0; ii < 4; ii++) av[ii] = tiles[(ti * 4 + ii) * 1028 + pl];
#pragma unroll
        for (int jj = 0; jj < 4; jj++) bv[jj] = tiles[(tj * 4 + jj) * 1028 + pl];
#pragma unroll
        for (int ii = 0; ii < 4; ii++)
#pragma unroll
            for (int jj = 0; jj < 4; jj++) accS[ii][jj] += av[ii] * bv[jj];
    }
#pragma unroll
    for (int mm = 0; mm < 8; mm++) {
        int m = (g << 3) + mm;
        float2 xv[4], yv[4];
#pragma unroll
        for (int ii = 0; ii < 4; ii++) xv[ii] = sX[(ti * 4 + ii) * 258 + m];
#pragma unroll
        for (int jj = 0; jj < 4; jj++) yv[jj] = sX[(tj * 4 + jj) * 258 + m];
#pragma unroll
        for (int ii = 0; ii < 4; ii++)
#pragma unroll
            for (int jj = 0; jj < 4; jj++)
                accF[ii][jj] += 2.0f * (xv[ii].x * yv[jj].x + xv[ii].y * yv[jj].y);
    }
    __syncthreads();
#pragma unroll
    for (int ii = 0; ii < 4; ii++)
#pragma unroll
        for (int jj = 0; jj < 4; jj++) {
            int pp = ((ti * 4 + ii) << 4) + tj * 4 + jj;
            tiles[pp * 33 + g] = accS[ii][jj] - accF[ii][jj] * (1.0f / 1024.0f);
        }
    __syncthreads();
    if (t < 256) {
        float ssum = 0.0f;
#pragma unroll
        for (int g2 = 0; g2 < 32; g2++) ssum += tiles[t * 33 + g2];
        int i = t >> 4, j = t & 15;
        ssum += sX[i * 258].x * sX[j * 258].x * (1.0f / 1024.0f);
        g_gram[(((b << 7) + c) << 8) + t] = ssum;
    }
}

// ---------------- A prep: transpose Xf -> realified split Ab ----------------
__global__ void k_prepA() {
    __shared__ float2 tile[32][33];
    int c0 = blockIdx.x << 5, r0 = blockIdx.y << 5;
    int tx = threadIdx.x, ty = threadIdx.y;
#pragma unroll
    for (int q = 0; q < 4; q++)
        tile[ty + (q << 3)][tx] = g_Xf[(long)(r0 + ty + (q << 3)) * 256 + c0 + tx];
    __syncthreads();
#pragma unroll
    for (int q = 0; q < 4; q++) {
        int m = c0 + ty + (q << 3);
        int row = r0 + tx;
        int bs = row >> 7, c = row & 127;
        float2 v = tile[tx][ty + (q << 3)];
        long base = ((long)m * 256 + bs) * 2 * 256;
        __nv_bfloat16 h, l;
        bf_split(v.x, h, l); g_Ab[base + c] = h;        g_Ab[base + 256 + c] = l;
        bf_split(v.y, h, l); g_Ab[base + 128 + c] = h;  g_Ab[base + 384 + c] = l;
    }
}

// ---------------- tensor-core GEMM: cp.async double-buffered, ldmatrix, fragment negation ----------------
template <int NT>
__global__ void __launch_bounds__(256) k_gemm() {
    extern __shared__ __nv_bfloat16 smem[];
    const unsigned SM_A = (unsigned)__cvta_generic_to_shared(smem);
    const unsigned SM_B = SM_A + 40960;

    int nb = blockIdx.x, mb = blockIdx.y, mo = blockIdx.z;
    int t = threadIdx.x;
    int wid = t >> 5, lane = t & 31;
    int wm = wid & 1, wn = wid >> 1;
    int g = lane >> 2, tq = lane & 3;

    int isImOut = (NT == 768) ? (nb >= 3 ? 1 : 0) : nb;
    int oI      = (NT == 768) ? (nb - (isImOut ? 3 : 0)) : 0;
    const __nv_bfloat16* Wbase = (NT == 768)
        ? (g_Wqc + ((long)mo * 3 + oI) * 2 * 32768)
        : (g_Woc + (long)mo * 2 * 32768);
    const __nv_bfloat16* Abase = g_Ab + ((long)mo * 256 + mb * 128) * 512;

    float acc[4][4][4];
#pragma unroll
    for (int i = 0; i < 4; i++)
#pragma unroll
        for (int j = 0; j < 4; j++)
#pragma unroll
            for (int r = 0; r < 4; r++) acc[i][j][r] = 0.0f;

    int lr = t & 127, lh = t >> 7;
    int aRow = (lane & 7) + ((lane >> 3) & 1) * 8;
    int aK   = (lane >> 4) * 8;
    int bRowOff = ((lane >> 4) << 3) + (lane & 7);
    int bK   = ((lane >> 3) & 1) * 8;

    auto load_stage = [&](int buf, int k0) {
        unsigned da = SM_A + (unsigned)(((buf * 2 + lh) * 128 + lr) * 80);
        const __nv_bfloat16* sa = Abase + (long)lr * 512 + lh * 256 + k0;
        cp16(da, sa); cp16(da + 16, sa + 8); cp16(da + 32, sa + 16); cp16(da + 48, sa + 24);
        int p = ((k0 >= 128) ? 1 : 0) ^ isImOut;
        unsigned db = SM_B + (unsigned)(((buf * 2 + lh) * 128 + lr) * 80);
        const __nv_bfloat16* sb = Wbase + (long)p * 32768 + (long)lr * 256 + lh * 128 + (k0 & 127);
        cp16(db, sb); cp16(db + 16, sb + 8); cp16(db + 32, sb + 16); cp16(db + 48, sb + 24);
    };

    load_stage(0, 0);
    asm volatile("cp.async.commit_group;");

    for (int it = 0; it < 8; it++) {
        if (it < 7) {
            load_stage((it + 1) & 1, (it + 1) * 32);
            asm volatile("cp.async.commit_group;");
            asm volatile("cp.async.wait_group 1;");
        } else {
            asm volatile("cp.async.wait_group 0;");
        }
        __syncthreads();
        int buf = it & 1;
        // negate B for the k-imag half feeding real outputs (exact sign flip on bf16x2)
        unsigned nm = (it >= 4 && isImOut == 0) ? 0x80008000u : 0u;
#pragma unroll
        for (int ks = 0; ks < 2; ks++) {
            int kb = ks * 16;
            unsigned ah[4][4], al[4][4], bh[4][2], bl[4][2];
#pragma unroll
            for (int mt = 0; mt < 4; mt++) {
                int row = wm * 64 + mt * 16 + aRow;
                int col = kb + aK;
                unsigned addr0 = SM_A + (unsigned)(((buf * 2 + 0) * 128 + row) * 80 + col * 2);
                unsigned addr1 = SM_A + (unsigned)(((buf * 2 + 1) * 128 + row) * 80 + col * 2);
                ldm_x4(ah[mt][0], ah[mt][1], ah[mt][2], ah[mt][3], addr0);
                ldm_x4(al[mt][0], al[mt][1], al[mt][2], al[mt][3], addr1);
            }
#pragma unroll
            for (int pr = 0; pr < 2; pr++) {
                int row = wn * 32 + pr * 16 + bRowOff;
                int col = kb + bK;
                unsigned addr0 = SM_B + (unsigned)(((buf * 2 + 0) * 128 + row) * 80 + col * 2);
                unsigned addr1 = SM_B + (unsigned)(((buf * 2 + 1) * 128 + row) * 80 + col * 2);
                ldm_x4(bh[2 * pr][0], bh[2 * pr][1], bh[2 * pr + 1][0], bh[2 * pr + 1][1], addr0);
                ldm_x4(bl[2 * pr][0], bl[2 * pr][1], bl[2 * pr + 1][0], bl[2 * pr + 1][1], addr1);
            }
#pragma unroll
            for (int nt = 0; nt < 4; nt++) {
                bh[nt][0] ^= nm; bh[nt][1] ^= nm;
                bl[nt][0] ^= nm; bl[nt][1] ^= nm;
            }
#define MMA(d, a, b0, b1)                                                     \
    asm volatile("mma.sync.aligned.m16n8k16.row.col.f32.bf16.bf16.f32 "       \
                 "{%0,%1,%2,%3}, {%4,%5,%6,%7}, {%8,%9}, {%0,%1,%2,%3};"      \
                 : "+f"(d[0]), "+f"(d[1]), "+f"(d[2]), "+f"(d[3])             \
                 : "r"(a[0]), "r"(a[1]), "r"(a[2]), "r"(a[3]), "r"(b0), "r"(b1))
#pragma unroll
            for (int mt = 0; mt < 4; mt++)
#pragma unroll
                for (int nt = 0; nt < 4; nt++) {
                    MMA(acc[mt][nt], ah[mt], bh[nt][0], bh[nt][1]);
                    MMA(acc[mt][nt], ah[mt], bl[nt][0], bl[nt][1]);
                    MMA(acc[mt][nt], al[mt], bh[nt][0], bh[nt][1]);
                }
#undef MMA
        }
        __syncthreads();
    }

    if (NT == 768) {
#pragma unroll
        for (int mt = 0; mt < 4; mt++)
#pragma unroll
            for (int nt = 0; nt < 4; nt++) {
                int c = wn * 32 + nt * 8 + 2 * tq;
#pragma unroll
                for (int rr = 0; rr < 2; rr++) {
                    int bs = mb * 128 + wm * 64 + mt * 16 + g + rr * 8;
                    float2 val = make_float2(acc[mt][nt][rr * 2], acc[mt][nt][rr * 2 + 1]);
                    long fidx = (long)bs * 65536 + (2L * mo + isImOut) * 128 + c;
                    if (oI == 0)
                        *(__nv_bfloat162*)&g_Fqh[fidx] = __floats2bfloat162_rn(val.x, val.y);
                    else if (oI == 1)
                        *(__nv_bfloat162*)&g_Fkh[fidx] = __floats2bfloat162_rn(val.x, val.y);
                    else {
                        float* vp = isImOut ? g_VeI : g_VeR;
                        *(float2*)&vp[((long)bs * 256 + mo) * 128 + c] = val;
                    }
                }
            }
    } else {
#pragma unroll
        for (int mt = 0; mt < 4; mt++)
#pragma unroll
            for (int nt = 0; nt < 4; nt++) {
                int row = mb * 128 + wm * 64 + mt * 16 + g;
                long base = ((long)mo * 256 + row) * NT + nb * 128 + wn * 32 + nt * 8 + 2 * tq;
                *(float2*)&g_C2o[base] = make_float2(acc[mt][nt][0], acc[mt][nt][1]);
                *(float2*)&g_C2o[base + 8L * NT] = make_float2(acc[mt][nt][2], acc[mt][nt][3]);
            }
    }
}

// ---------------- scores: partial feature-Gram (8x more CTAs) ----------------
__global__ void k_scores_part() {
    int b = blockIdx.x, n = blockIdx.y, pt = blockIdx.z;
    __shared__ float sq[16 * 132], sk[16 * 132];
    int t = threadIdx.x;
    int i = t >> 4, j = t & 15;
    float D = 0.0f;

    for (int ch0 = 0; ch0 < 8; ch0++) {
        int ch = pt * 8 + ch0;
#pragma unroll
        for (int k = 0; k < 4; k++) {
            int e = t + (k << 8);
            int dp = e & 7, mcL = (e >> 3) & 7, ii = e >> 6;
            long ga = ((long)((b << 4) + ii) * 512 + (ch << 3) + mcL) * 128 + (n << 4) + (dp << 1);
            int sa = ii * 132 + (mcL << 4) + (dp << 1);
            __nv_bfloat162 q2 = *(const __nv_bfloat162*)&g_Fqh[ga];
            __nv_bfloat162 k2 = *(const __nv_bfloat162*)&g_Fkh[ga];
            *(float2*)&sq[sa] = __bfloat1622float2(q2);
            *(float2*)&sk[sa] = __bfloat1622float2(k2);
        }
        __syncthreads();
        const float4* aq = (const float4*)(sq + i * 132);
        const float4* ak = (const float4*)(sk + j * 132);
#pragma unroll
        for (int r = 0; r < 32; r++) {
            float4 a = aq[r], bb = ak[r];
            D += a.x * bb.x + a.y * bb.y + a.z * bb.z + a.w * bb.w;
        }
        __syncthreads();
    }
    g_Dpart[(((b * 8 + n) * 8 + pt) << 8) + t] = D;
}

// ---------------- scores finalize: reduce partials + bias + softmax ----------------
__global__ void k_scores_fin(const float* __restrict__ amask) {
    int b = blockIdx.x, n = blockIdx.y;
    int t = threadIdx.x;
    float D = 0.0f;
#pragma unroll
    for (int p = 0; p < 8; p++)
        D += g_Dpart[(((b * 8 + n) * 8 + p) << 8) + t];

    float gsum = 0.0f;
#pragma unroll
    for (int d = 0; d < 16; d++)
        gsum += g_gram[(((b << 7) + (n << 4) + d) << 8) + t];

    float s = (gsum + D * (1.0f / 1024.0f)) * (1.0f / 4096.0f);
    s += amask[(((b & 3) * 8 + n) << 8) + t] + g_cpb[(n << 8) + t];
    float mx = s;
#pragma unroll
    for (int off = 8; off; off >>= 1) mx = fmaxf(mx, __shfl_xor_sync(0xffffffffu, mx, off));
    float e = expf(s - mx);
    float su = e;
#pragma unroll
    for (int off = 8; off; off >>= 1) su += __shfl_xor_sync(0xffffffffu, su, off);
    g_attn[((b * 8 + n) << 8) + t] = e / su;
}

// ---------------- attn x Veff -> realified split A for out GEMM ----------------
__global__ void k_av() {
    int b = blockIdx.x, mch = blockIdx.y;
    __shared__ float2 sV[16][2][128];
    __shared__ float sA[2048];
    int t = threadIdx.x;
#pragma unroll
    for (int k = 0; k < 8; k++) sA[t + (k << 8)] = g_attn[b * 2048 + t + (k << 8)];
#pragma unroll
    for (int k = 0; k < 16; k++) {
        int e = t + (k << 8);
        int c = e & 127, mo = (e >> 7) & 1, j = e >> 8;
        long vi = ((long)((b << 4) + j) * 256 + (mch << 1) + mo) * 128 + c;
        sV[j][mo][c] = make_float2(g_VeR[vi], g_VeI[vi]);
    }
    __syncthreads();
    int c = t & 127, mo = t >> 7;
    int n = c >> 4;
    float2 acc[16];
#pragma unroll
    for (int ii = 0; ii < 16; ii++) acc[ii] = make_float2(0.0f, 0.0f);
#pragma unroll
    for (int jj = 0; jj < 16; jj++) {
        float2 v = sV[jj][mo][c];
#pragma unroll
        for (int ii = 0; ii < 16; ii++) {
            float a = sA[(n << 8) + (ii << 4) + jj];
            acc[ii].x += a * v.x;
            acc[ii].y += a * v.y;
        }
    }
    int m = (mch << 1) + mo;
#pragma unroll
    for (int ii = 0; ii < 16; ii++) {
        int bs = (b << 4) + ii;
        long base = ((long)m * 256 + bs) * 2 * 256;
        __nv_bfloat16 h, l;
        bf_split(acc[ii].x, h, l); g_Ab[base + c] = h;       g_Ab[base + 256 + c] = l;
        bf_split(acc[ii].y, h, l); g_Ab[base + 128 + c] = h; g_Ab[base + 384 + c] = l;
    }
}

// ---------------- inverse irfft2, 8 channels/block, direct C2o read, fused un-shift ----------------
__global__ void k_inv2(float* __restrict__ dout) {
    int bs = blockIdx.x, og = blockIdx.y;
    __shared__ float2 sS[8][257];
    __shared__ float2 Gs[32][17];
    __shared__ float2 ytabs[512];
    __shared__ float2 tw[32];
    int t = threadIdx.x;
    if (t < 32) tw[t] = g_tw[t];
    ytabs[t]       = g_ytab[t];
    ytabs[t + 256] = g_ytab[t + 256];
    {
        long base = (long)t * 65536 + bs * 256 + og * 8;
        float re[8], im[8];
#pragma unroll
        for (int q = 0; q < 2; q++) {
            *(float4*)&re[q * 4] = *(const float4*)&g_C2o[base + q * 4];
            *(float4*)&im[q * 4] = *(const float4*)&g_C2o[base + 128 + q * 4];
        }
#pragma unroll
        for (int ol = 0; ol < 8; ol++)
            sS[ol][t] = make_float2(re[ol], im[ol]);
    }
    __syncthreads();

    int b = bs >> 4, s = bs & 15, qx = s >> 2, qy = s & 3;
    for (int o = 0; o < 8; o++) {
#pragma unroll
        for (int q = 0; q < 2; q++) {
            int idx = t + (q << 8);
            int u = idx >> 4, ky = idx & 15;
            float gr = 0.0f, gi = 0.0f;
            int a = 0;
#pragma unroll
            for (int kx = 0; kx < 16; kx++) {
                float2 sv = sS[o][(kx << 4) + ky];
                float2 w = tw[a];
                gr += sv.x * w.x - sv.y * w.y;
                gi += sv.x * w.y + sv.y * w.x;
                a = (a + u) & 31;
            }
            Gs[u][ky] = make_float2(gr, gi);
        }
        __syncthreads();
#pragma unroll
        for (int q = 0; q < 4; q++) {
            int idx = t + (q << 8);
            int u = idx >> 5, v = idx & 31;
            float acc = 0.0f;
#pragma unroll
            for (int ky = 0; ky < 16; ky++) {
                float2 gv = Gs[u][ky];
                float2 w = ytabs[(ky << 5) + v];
                acc += gv.x * w.x - gv.y * w.y;
            }
            float y = acc * (2.0f / 1024.0f);
            int I = ((qx << 5) + u + 16) & 127;
            int J = ((qy << 5) + v + 16) & 127;
            int s2 = ((I >> 5) << 2) | (J >> 5);
            long off = ((long)(b * 16 + s2) * 128) * NP + ((I & 31) << 5) + (J & 31);
            dout[off + (long)(og * 8 + o) * NP] = y;
        }
        __syncthreads();
    }
}

// ---------------- launch ----------------
extern "C" void kernel_launch(void* const* d_in, const int* in_sizes, int n_in,
                              void* d_out, int out_size) {
    const float* seq    = (const float*)d_in[0];
    const float* qkv_wr = (const float*)d_in[1];
    const float* qkv_wi = (const float*)d_in[2];
    const float* out_wr = (const float*)d_in[3];
    const float* out_wi = (const float*)d_in[4];
    const float* cpb_w1 = (const float*)d_in[5];
    const float* cpb_b1 = (const float*)d_in[6];
    const float* cpb_w2 = (const float*)d_in[7];
    const float* amask  = (const float*)d_in[8];
    float* outp = (float*)d_out;

    const int FG_SMEM = 16 * 1028 * 4 + 16 * 258 * 8 + 16 * 16 * 33 * 8;  // 166400 B
    cudaFuncSetAttribute(k_fg, cudaFuncAttributeMaxDynamicSharedMemorySize, FG_SMEM);
    const int GEMM_SMEM = 81920;
    cudaFuncSetAttribute(k_gemm<768>, cudaFuncAttributeMaxDynamicSharedMemorySize, GEMM_SMEM);
    cudaFuncSetAttribute(k_gemm<256>, cudaFuncAttributeMaxDynamicSharedMemorySize, GEMM_SMEM);

    k_init<<<2, 512>>>(cpb_w1, cpb_b1, cpb_w2);
    k_wprep<<<dim3(384, 8), 256>>>(qkv_wr, qkv_wi, 0);
    k_wprep<<<dim3(128, 8), 256>>>(out_wr, out_wi, 1);

    k_fg<<<dim3(16, 128), 512, FG_SMEM>>>(seq);
    k_prepA<<<dim3(8, 1024), dim3(32, 8)>>>();

    k_gemm<768><<<dim3(6, 2, 256), 256, GEMM_SMEM>>>();

    k_scores_part<<<dim3(16, 8, 8), 256>>>();
    k_scores_fin<<<dim3(16, 8), 256>>>(amask);
    k_av<<<dim3(16, 128), 256>>>();

    k_gemm<256><<<dim3(2, 2, 256), 256, GEMM_SMEM>>>();
    k_inv2<<<dim3(256, 16), 256>>>(outp);
}